// round 12
// baseline (speedup 1.0000x reference)
#include <cuda_runtime.h>
#include <cuda_fp16.h>
#include <math.h>
#include <stdint.h>

#define Bsz 2
#define Sseq 2048
#define Dmodel 2048
#define Hheads 16
#define HDdim 128
#define Mrows (Bsz * Sseq)   // 4096

// ---------------- scratch (fp16 payloads in ushort arrays) ----------------
__device__ unsigned short g_xhi[Mrows * Dmodel];
__device__ unsigned short g_qhi[Mrows * Dmodel];
__device__ unsigned short g_khi[Mrows * Dmodel];
__device__ unsigned short g_vhi[Mrows * Dmodel];
__device__ unsigned short g_yhi[Mrows * Dmodel];
__device__ unsigned short g_wq[Dmodel * Dmodel];
__device__ unsigned short g_wk[Dmodel * Dmodel];
__device__ unsigned short g_wv[Dmodel * Dmodel];
__device__ unsigned short g_wo[Dmodel * Dmodel];

// ---------------- helpers ----------------
__device__ __forceinline__ uint32_t smem_to_u32(const void* p) {
    uint32_t a;
    asm("{ .reg .u64 t; cvta.to.shared.u64 t, %1; cvt.u32.u64 %0, t; }" : "=r"(a) : "l"(p));
    return a;
}

#define CP_ASYNC16(dst_u32, src_ptr) \
    asm volatile("cp.async.cg.shared.global [%0], [%1], 16;" :: "r"(dst_u32), "l"(src_ptr))
#define CP_COMMIT() asm volatile("cp.async.commit_group;")
#define CP_WAIT2()  asm volatile("cp.async.wait_group 2;")
#define CP_WAIT1()  asm volatile("cp.async.wait_group 1;")
#define CP_WAIT0()  asm volatile("cp.async.wait_group 0;")

// tail-aware wait: guarantees the chunk consumed this iteration has landed
#define CP_WAIT_TAIL(ch, nch) do { \
    if ((ch) + 1 == (nch)) { CP_WAIT0(); } \
    else if ((ch) + 2 == (nch)) { CP_WAIT1(); } \
    else { CP_WAIT2(); } \
} while (0)

#define LDSM_X4(r0, r1, r2, r3, addr) \
    asm volatile("ldmatrix.sync.aligned.m8n8.x4.shared.b16 {%0,%1,%2,%3}, [%4];" \
                 : "=r"(r0), "=r"(r1), "=r"(r2), "=r"(r3) : "r"(addr))
#define LDSM_X4_T(r0, r1, r2, r3, addr) \
    asm volatile("ldmatrix.sync.aligned.m8n8.x4.trans.shared.b16 {%0,%1,%2,%3}, [%4];" \
                 : "=r"(r0), "=r"(r1), "=r"(r2), "=r"(r3) : "r"(addr))

#define MMA_F16(c, a, b) \
    asm volatile("mma.sync.aligned.m16n8k16.row.col.f32.f16.f16.f32 " \
                 "{%0,%1,%2,%3},{%4,%5,%6,%7},{%8,%9},{%0,%1,%2,%3};" \
                 : "+f"((c)[0]), "+f"((c)[1]), "+f"((c)[2]), "+f"((c)[3]) \
                 : "r"((a)[0]), "r"((a)[1]), "r"((a)[2]), "r"((a)[3]), \
                   "r"((b)[0]), "r"((b)[1]))

__device__ __forceinline__ float fast_ex2(float x) {
    float y; asm("ex2.approx.f32 %0, %1;" : "=f"(y) : "f"(x)); return y;
}

__device__ __forceinline__ uint32_t pack_f16(float a, float b) {
    __half2 hv = __floats2half2_rn(a, b);
    return *reinterpret_cast<uint32_t*>(&hv);
}

// ---------------------------------------------------------------------------
// converts: fp32 -> fp16
// ---------------------------------------------------------------------------
__global__ __launch_bounds__(256) void conv_x(const float* __restrict__ x) {
    int i = blockIdx.x * blockDim.x + threadIdx.x;
    float4 v = ((const float4*)x)[i];
    ((uint2*)g_xhi)[i] = make_uint2(pack_f16(v.x, v.y), pack_f16(v.z, v.w));
}

__global__ __launch_bounds__(256) void conv_w(const float* __restrict__ Wq,
                                              const float* __restrict__ Wk,
                                              const float* __restrict__ Wv,
                                              const float* __restrict__ Wo) {
    int i = blockIdx.x * blockDim.x + threadIdx.x;
    int z = blockIdx.z;
    const float* src = (z == 0) ? Wq : (z == 1) ? Wk : (z == 2) ? Wv : Wo;
    unsigned short* dst = (z == 0) ? g_wq : (z == 1) ? g_wk : (z == 2) ? g_wv : g_wo;
    float4 v = ((const float4*)src)[i];
    ((uint2*)dst)[i] = make_uint2(pack_f16(v.x, v.y), pack_f16(v.z, v.w));
}

// ---------------------------------------------------------------------------
// GEMM: C[128x128 tile] = A[M,K] * B[N,K]^T, single fp16 pass.
// 128 threads, 4 warps (2x2 grid), warp tile 64x64. K-chunks of 64,
// 3-stage cp.async pipeline (tail-aware waits); 2 CTAs/SM.
// OUT_MODE: 0 = fp32 C, 2 = fp16 (scaled by 'oscale').
// ---------------------------------------------------------------------------
#define GROWB 144
#define TILE_B (128 * GROWB)           // 18432
#define G_STAGE_B (2 * TILE_B)         // 36864: A, B
#define G_SMEM (3 * G_STAGE_B)         // 110592

__device__ __forceinline__ void gemm_issue(
    uint32_t sbase, int buf, int tid,
    const unsigned short* __restrict__ A, const unsigned short* __restrict__ B,
    int rowBase, int colBase, int ch)
{
    const size_t kOff = (size_t)ch * 64;
    const uint32_t stage = sbase + buf * G_STAGE_B;
    const unsigned short* srcs[2] = {
        A + (size_t)rowBase * Dmodel + kOff,
        B + (size_t)colBase * Dmodel + kOff };
#pragma unroll
    for (int t = 0; t < 2; t++) {
        const unsigned short* src = srcs[t];
        const uint32_t dstT = stage + t * TILE_B;
#pragma unroll
        for (int it = 0; it < 8; it++) {
            int idx = it * 128 + tid;   // 0..1023
            int r = idx >> 3;
            int j = idx & 7;
            CP_ASYNC16(dstT + r * GROWB + j * 16, src + (size_t)r * Dmodel + j * 8);
        }
    }
    CP_COMMIT();
}

template<int OUT_MODE>
__device__ __forceinline__ void gemm_core(
    const unsigned short* __restrict__ A, const unsigned short* __restrict__ B,
    float* __restrict__ C, unsigned short* __restrict__ Cf, float oscale)
{
    extern __shared__ char smem[];
    const uint32_t sbase = smem_to_u32(smem);
    const int tid = threadIdx.x;
    const int wid = tid >> 5;
    const int lane = tid & 31;

    const int rowBase = blockIdx.y * 128;
    const int colBase = blockIdx.x * 128;
    const int m0 = (wid & 1) * 64;
    const int n0 = (wid >> 1) * 64;

    const int lr = (lane & 7) + (lane & 8);
    const int lk = (lane >> 4) << 3;

    float acc[4][8][4];
#pragma unroll
    for (int mt = 0; mt < 4; mt++)
#pragma unroll
        for (int nt = 0; nt < 8; nt++)
#pragma unroll
            for (int q = 0; q < 4; q++) acc[mt][nt][q] = 0.f;

    const int nch = Dmodel / 64;   // 32
    gemm_issue(sbase, 0, tid, A, B, rowBase, colBase, 0);
    gemm_issue(sbase, 1, tid, A, B, rowBase, colBase, 1);
    gemm_issue(sbase, 2, tid, A, B, rowBase, colBase, 2);

    int buf = 0;
    for (int ch = 0; ch < nch; ch++) {
        CP_WAIT_TAIL(ch, nch);
        __syncthreads();

        const uint32_t aB = sbase + buf * G_STAGE_B;
        const uint32_t bB = aB + TILE_B;

#pragma unroll
        for (int ks = 0; ks < 4; ks++) {
            const int k0 = ks * 16;
            uint32_t af[4][4];
#pragma unroll
            for (int mt = 0; mt < 4; mt++) {
                uint32_t off = (m0 + mt * 16 + lr) * GROWB + (k0 + lk) * 2;
                LDSM_X4(af[mt][0], af[mt][1], af[mt][2], af[mt][3], aB + off);
            }
            uint32_t bf[8][2];
#pragma unroll
            for (int jp = 0; jp < 4; jp++) {
                uint32_t off = (n0 + jp * 16 + lr) * GROWB + (k0 + lk) * 2;
                uint32_t r0, r1, r2, r3;
                LDSM_X4(r0, r1, r2, r3, bB + off);
                bf[2 * jp][0] = r0; bf[2 * jp][1] = r2;
                bf[2 * jp + 1][0] = r1; bf[2 * jp + 1][1] = r3;
            }
#pragma unroll
            for (int mt = 0; mt < 4; mt++)
#pragma unroll
                for (int nt = 0; nt < 8; nt++) MMA_F16(acc[mt][nt], af[mt], bf[nt]);
        }
        __syncthreads();
        if (ch + 3 < nch)
            gemm_issue(sbase, buf, tid, A, B, rowBase, colBase, ch + 3);
        buf = (buf == 2) ? 0 : buf + 1;
    }

    const int cr = lane >> 2;
    const int cc = (lane & 3) * 2;
#pragma unroll
    for (int mt = 0; mt < 4; mt++) {
#pragma unroll
        for (int nt = 0; nt < 8; nt++) {
            const int row = rowBase + m0 + mt * 16 + cr;
            const int col = colBase + n0 + nt * 8 + cc;
            if (OUT_MODE == 2) {
                *(uint32_t*)(Cf + (size_t)row * Dmodel + col) =
                    pack_f16(acc[mt][nt][0] * oscale, acc[mt][nt][1] * oscale);
                *(uint32_t*)(Cf + (size_t)(row + 8) * Dmodel + col) =
                    pack_f16(acc[mt][nt][2] * oscale, acc[mt][nt][3] * oscale);
            } else {
                *(float2*)&C[(size_t)row * Dmodel + col] = make_float2(acc[mt][nt][0], acc[mt][nt][1]);
                *(float2*)&C[(size_t)(row + 8) * Dmodel + col] = make_float2(acc[mt][nt][2], acc[mt][nt][3]);
            }
        }
    }
}

__global__ __launch_bounds__(128, 2) void gemm_qkv() {
    const int z = blockIdx.z;
    const unsigned short* B = (z == 0) ? g_wq : (z == 1) ? g_wk : g_wv;
    unsigned short* cf = (z == 0) ? g_qhi : (z == 1) ? g_khi : g_vhi;
    const float osc = (z == 0) ? (1.4426950408889634f * 0.08838834764831845f) : 1.0f;
    gemm_core<2>(g_xhi, B, nullptr, cf, osc);
}

__global__ __launch_bounds__(128, 2) void gemm_wo(float* __restrict__ out) {
    gemm_core<0>(g_yhi, g_wo, out, nullptr, 1.0f);
}

// ---------------------------------------------------------------------------
// Flash attention: 64-query CTAs, 128 threads (4 warps), 2 CTAs/SM.
// Q pre-scaled fp16; single-pass S and PV; 3-stage KV pipeline (tail-aware).
// ---------------------------------------------------------------------------
#define ASTRIDE 272
#define ATILE_B (64 * ASTRIDE)         // 17408
#define ASTAGE_B (2 * ATILE_B)         // 34816: K, V
#define ATTN_SMEM (3 * ASTAGE_B)       // 104448

__device__ __forceinline__ void attn_issue_kv(uint32_t sbase, int buf, int tid,
                                              size_t hbase, int kt)
{
    const unsigned short* srcs[2] = {g_khi, g_vhi};
    const uint32_t stage = sbase + buf * ASTAGE_B;
#pragma unroll
    for (int t = 0; t < 2; t++) {
        const unsigned short* src = srcs[t] + hbase + (size_t)(kt * 64) * Dmodel;
        const uint32_t dstT = stage + t * ATILE_B;
#pragma unroll
        for (int it = 0; it < 8; it++) {
            int idx = it * 128 + tid;
            int r = idx >> 4;
            int j = idx & 15;
            CP_ASYNC16(dstT + r * ASTRIDE + j * 16, src + (size_t)r * Dmodel + j * 8);
        }
    }
    CP_COMMIT();
}

__global__ __launch_bounds__(128, 2) void attn_mma()
{
    extern __shared__ char smem[];
    const uint32_t sbase = smem_to_u32(smem);
    const int tid = threadIdx.x;
    const int wid = tid >> 5;
    const int lane = tid & 31;

    const int qt = (gridDim.x - 1) - blockIdx.x;   // heavy tiles first
    const int h = blockIdx.y;
    const int b = blockIdx.z;
    const size_t hbase = ((size_t)b * Sseq) * Dmodel + (size_t)h * HDdim;

    const int lr = (lane & 7) + (lane & 8);
    const int lk = (lane >> 4) << 3;

    // stage Q (64 x 128 fp16, pre-scaled) through stage0 smem into frags
    {
#pragma unroll
        for (int it = 0; it < 8; it++) {
            int idx = it * 128 + tid;
            int r = idx >> 4;
            int j = idx & 15;
            const size_t goff = hbase + (size_t)(qt * 64 + r) * Dmodel + j * 8;
            CP_ASYNC16(sbase + r * ASTRIDE + j * 16, g_qhi + goff);
        }
        CP_COMMIT(); CP_WAIT0();
        __syncthreads();
    }
    uint32_t qf[8][4];
#pragma unroll
    for (int ks = 0; ks < 8; ks++) {
        uint32_t off = (wid * 16 + lr) * ASTRIDE + (ks * 16 + lk) * 2;
        LDSM_X4(qf[ks][0], qf[ks][1], qf[ks][2], qf[ks][3], sbase + off);
    }
    __syncthreads();

    float oacc[16][4];
#pragma unroll
    for (int nt = 0; nt < 16; nt++)
#pragma unroll
        for (int q = 0; q < 4; q++) oacc[nt][q] = 0.f;
    float m0 = -1e30f, m1 = -1e30f, l0 = 0.f, l1 = 0.f;

    const int nkt = qt + 1;
    attn_issue_kv(sbase, 0, tid, hbase, 0);
    if (nkt > 1) attn_issue_kv(sbase, 1, tid, hbase, 1);
    if (nkt > 2) attn_issue_kv(sbase, 2, tid, hbase, 2);

    const int row0 = qt * 64 + wid * 16 + (lane >> 2);

    int buf = 0;
    for (int kt = 0; kt < nkt; kt++) {
        CP_WAIT_TAIL(kt, nkt);
        __syncthreads();

        const uint32_t stage = sbase + buf * ASTAGE_B;
        const uint32_t kB = stage;
        const uint32_t vB = stage + ATILE_B;

        // S = Q K^T (Q pre-scaled; S already in log2 units)
        float sacc[8][4];
#pragma unroll
        for (int nt = 0; nt < 8; nt++)
#pragma unroll
            for (int q = 0; q < 4; q++) sacc[nt][q] = 0.f;
#pragma unroll
        for (int ks = 0; ks < 8; ks++) {
            uint32_t bh[8][2];
#pragma unroll
            for (int jp = 0; jp < 4; jp++) {
                uint32_t off = (jp * 16 + lr) * ASTRIDE + (ks * 16 + lk) * 2;
                uint32_t r0, r1, r2, r3;
                LDSM_X4(r0, r1, r2, r3, kB + off);
                bh[2 * jp][0] = r0; bh[2 * jp][1] = r2;
                bh[2 * jp + 1][0] = r1; bh[2 * jp + 1][1] = r3;
            }
#pragma unroll
            for (int nt = 0; nt < 8; nt++) MMA_F16(sacc[nt], qf[ks], bh[nt]);
        }

        // causal mask: only the diagonal k-tile needs it
        if (kt == qt) {
            const int col0 = kt * 64 + 2 * (lane & 3);
#pragma unroll
            for (int nt = 0; nt < 8; nt++) {
#pragma unroll
                for (int e = 0; e < 2; e++) {
                    if (col0 + nt * 8 + e > row0) sacc[nt][e] = -1e30f;
                    if (col0 + nt * 8 + e > row0 + 8) sacc[nt][2 + e] = -1e30f;
                }
            }
        }

        // online softmax in base-2
        float mx0 = -1e30f, mx1 = -1e30f;
#pragma unroll
        for (int nt = 0; nt < 8; nt++) {
            mx0 = fmaxf(mx0, fmaxf(sacc[nt][0], sacc[nt][1]));
            mx1 = fmaxf(mx1, fmaxf(sacc[nt][2], sacc[nt][3]));
        }
        mx0 = fmaxf(mx0, __shfl_xor_sync(0xffffffffu, mx0, 1));
        mx0 = fmaxf(mx0, __shfl_xor_sync(0xffffffffu, mx0, 2));
        mx1 = fmaxf(mx1, __shfl_xor_sync(0xffffffffu, mx1, 1));
        mx1 = fmaxf(mx1, __shfl_xor_sync(0xffffffffu, mx1, 2));
        float mn0 = fmaxf(m0, mx0), mn1 = fmaxf(m1, mx1);
        float a0 = fast_ex2(m0 - mn0), a1 = fast_ex2(m1 - mn1);
#pragma unroll
        for (int nt = 0; nt < 16; nt++) {
            oacc[nt][0] *= a0; oacc[nt][1] *= a0;
            oacc[nt][2] *= a1; oacc[nt][3] *= a1;
        }
        float ls0 = 0.f, ls1 = 0.f;
#pragma unroll
        for (int nt = 0; nt < 8; nt++) {
            float p0 = fast_ex2(sacc[nt][0] - mn0);
            float p1 = fast_ex2(sacc[nt][1] - mn0);
            float p2 = fast_ex2(sacc[nt][2] - mn1);
            float p3 = fast_ex2(sacc[nt][3] - mn1);
            sacc[nt][0] = p0; sacc[nt][1] = p1; sacc[nt][2] = p2; sacc[nt][3] = p3;
            ls0 += p0 + p1; ls1 += p2 + p3;
        }
        ls0 += __shfl_xor_sync(0xffffffffu, ls0, 1);
        ls0 += __shfl_xor_sync(0xffffffffu, ls0, 2);
        ls1 += __shfl_xor_sync(0xffffffffu, ls1, 1);
        ls1 += __shfl_xor_sync(0xffffffffu, ls1, 2);
        l0 = l0 * a0 + ls0; l1 = l1 * a1 + ls1;
        m0 = mn0; m1 = mn1;

        // O += P V, single fp16 pass
#pragma unroll
        for (int kstep = 0; kstep < 4; kstep++) {
            uint32_t ph[4];
            ph[0] = pack_f16(sacc[2 * kstep][0], sacc[2 * kstep][1]);
            ph[1] = pack_f16(sacc[2 * kstep][2], sacc[2 * kstep][3]);
            ph[2] = pack_f16(sacc[2 * kstep + 1][0], sacc[2 * kstep + 1][1]);
            ph[3] = pack_f16(sacc[2 * kstep + 1][2], sacc[2 * kstep + 1][3]);
#pragma unroll
            for (int db = 0; db < 2; db++) {
                uint32_t bv[8][2];
#pragma unroll
                for (int dpi = 0; dpi < 4; dpi++) {
                    const int dp = db * 4 + dpi;
                    uint32_t off = (kstep * 16 + lr) * ASTRIDE + (dp * 16 + lk) * 2;
                    uint32_t v0, v1, v2, v3;
                    LDSM_X4_T(v0, v1, v2, v3, vB + off);
                    bv[2 * dpi][0] = v0; bv[2 * dpi][1] = v1;
                    bv[2 * dpi + 1][0] = v2; bv[2 * dpi + 1][1] = v3;
                }
#pragma unroll
                for (int dpi = 0; dpi < 4; dpi++) {
                    MMA_F16(oacc[2 * (db * 4 + dpi)], ph, bv[2 * dpi]);
                    MMA_F16(oacc[2 * (db * 4 + dpi) + 1], ph, bv[2 * dpi + 1]);
                }
            }
        }

        __syncthreads();
        if (kt + 3 < nkt)
            attn_issue_kv(sbase, buf, tid, hbase, kt + 3);
        buf = (buf == 2) ? 0 : buf + 1;
    }

    const float inv0 = 1.f / l0;
    const float inv1 = 1.f / l1;
#pragma unroll
    for (int nt = 0; nt < 16; nt++) {
        const int col = nt * 8 + 2 * (lane & 3);
        const size_t i0 = ((size_t)b * Sseq + row0) * Dmodel + h * HDdim + col;
        const size_t i1 = ((size_t)b * Sseq + row0 + 8) * Dmodel + h * HDdim + col;
        *(uint32_t*)(g_yhi + i0) = pack_f16(oacc[nt][0] * inv0, oacc[nt][1] * inv0);
        *(uint32_t*)(g_yhi + i1) = pack_f16(oacc[nt][2] * inv1, oacc[nt][3] * inv1);
    }
}

// ---------------------------------------------------------------------------
// launch
// ---------------------------------------------------------------------------
extern "C" void kernel_launch(void* const* d_in, const int* in_sizes, int n_in,
                              void* d_out, int out_size)
{
    (void)in_sizes; (void)n_in; (void)out_size;
    const float* x  = (const float*)d_in[0];
    const float* Wq = (const float*)d_in[2];
    const float* Wk = (const float*)d_in[3];
    const float* Wv = (const float*)d_in[4];
    const float* Wo = (const float*)d_in[5];
    float* out = (float*)d_out;

    cudaFuncSetAttribute(gemm_qkv, cudaFuncAttributeMaxDynamicSharedMemorySize, G_SMEM);
    cudaFuncSetAttribute(gemm_wo, cudaFuncAttributeMaxDynamicSharedMemorySize, G_SMEM);
    cudaFuncSetAttribute(attn_mma, cudaFuncAttributeMaxDynamicSharedMemorySize, ATTN_SMEM);

    const int nX4 = Mrows * Dmodel / 4;
    const int nW4 = Dmodel * Dmodel / 4;

    conv_x<<<nX4 / 256, 256>>>(x);
    conv_w<<<dim3(nW4 / 256, 1, 4), 256>>>(Wq, Wk, Wv, Wo);

    gemm_qkv<<<dim3(Dmodel / 128, Mrows / 128, 3), 128, G_SMEM>>>();
    attn_mma<<<dim3(Sseq / 64, Hheads, Bsz), 128, ATTN_SMEM>>>();
    gemm_wo<<<dim3(Dmodel / 128, Mrows / 128, 1), 128, G_SMEM>>>(out);
}

// round 13
// speedup vs baseline: 1.0379x; 1.0379x over previous
#include <cuda_runtime.h>
#include <cuda_fp16.h>
#include <math.h>
#include <stdint.h>

#define Bsz 2
#define Sseq 2048
#define Dmodel 2048
#define Hheads 16
#define HDdim 128
#define Mrows (Bsz * Sseq)   // 4096

// ---------------- scratch (fp16 payloads in ushort arrays) ----------------
__device__ unsigned short g_xhi[Mrows * Dmodel];
__device__ unsigned short g_qhi[Mrows * Dmodel];
__device__ unsigned short g_khi[Mrows * Dmodel];
__device__ unsigned short g_vhi[Mrows * Dmodel];
__device__ unsigned short g_yhi[Mrows * Dmodel];
__device__ unsigned short g_wq[Dmodel * Dmodel];
__device__ unsigned short g_wk[Dmodel * Dmodel];
__device__ unsigned short g_wv[Dmodel * Dmodel];
__device__ unsigned short g_wo[Dmodel * Dmodel];

// ---------------- helpers ----------------
__device__ __forceinline__ uint32_t smem_to_u32(const void* p) {
    uint32_t a;
    asm("{ .reg .u64 t; cvta.to.shared.u64 t, %1; cvt.u32.u64 %0, t; }" : "=r"(a) : "l"(p));
    return a;
}

#define CP_ASYNC16(dst_u32, src_ptr) \
    asm volatile("cp.async.cg.shared.global [%0], [%1], 16;" :: "r"(dst_u32), "l"(src_ptr))
#define CP_COMMIT() asm volatile("cp.async.commit_group;")
#define CP_WAIT2()  asm volatile("cp.async.wait_group 2;")
#define CP_WAIT1()  asm volatile("cp.async.wait_group 1;")
#define CP_WAIT0()  asm volatile("cp.async.wait_group 0;")

// tail-aware wait: guarantees the chunk consumed this iteration has landed
#define CP_WAIT_TAIL(ch, nch) do { \
    if ((ch) + 1 == (nch)) { CP_WAIT0(); } \
    else if ((ch) + 2 == (nch)) { CP_WAIT1(); } \
    else { CP_WAIT2(); } \
} while (0)

#define LDSM_X4(r0, r1, r2, r3, addr) \
    asm volatile("ldmatrix.sync.aligned.m8n8.x4.shared.b16 {%0,%1,%2,%3}, [%4];" \
                 : "=r"(r0), "=r"(r1), "=r"(r2), "=r"(r3) : "r"(addr))
#define LDSM_X4_T(r0, r1, r2, r3, addr) \
    asm volatile("ldmatrix.sync.aligned.m8n8.x4.trans.shared.b16 {%0,%1,%2,%3}, [%4];" \
                 : "=r"(r0), "=r"(r1), "=r"(r2), "=r"(r3) : "r"(addr))

#define MMA_F16(c, a, b) \
    asm volatile("mma.sync.aligned.m16n8k16.row.col.f32.f16.f16.f32 " \
                 "{%0,%1,%2,%3},{%4,%5,%6,%7},{%8,%9},{%0,%1,%2,%3};" \
                 : "+f"((c)[0]), "+f"((c)[1]), "+f"((c)[2]), "+f"((c)[3]) \
                 : "r"((a)[0]), "r"((a)[1]), "r"((a)[2]), "r"((a)[3]), \
                   "r"((b)[0]), "r"((b)[1]))

__device__ __forceinline__ float fast_ex2(float x) {
    float y; asm("ex2.approx.f32 %0, %1;" : "=f"(y) : "f"(x)); return y;
}

__device__ __forceinline__ uint32_t pack_f16(float a, float b) {
    __half2 hv = __floats2half2_rn(a, b);
    return *reinterpret_cast<uint32_t*>(&hv);
}

// ---------------------------------------------------------------------------
// converts: fp32 -> fp16
// ---------------------------------------------------------------------------
__global__ __launch_bounds__(256) void conv_x(const float* __restrict__ x) {
    int i = blockIdx.x * blockDim.x + threadIdx.x;
    float4 v = ((const float4*)x)[i];
    ((uint2*)g_xhi)[i] = make_uint2(pack_f16(v.x, v.y), pack_f16(v.z, v.w));
}

__global__ __launch_bounds__(256) void conv_w(const float* __restrict__ Wq,
                                              const float* __restrict__ Wk,
                                              const float* __restrict__ Wv,
                                              const float* __restrict__ Wo) {
    int i = blockIdx.x * blockDim.x + threadIdx.x;
    int z = blockIdx.z;
    const float* src = (z == 0) ? Wq : (z == 1) ? Wk : (z == 2) ? Wv : Wo;
    unsigned short* dst = (z == 0) ? g_wq : (z == 1) ? g_wk : (z == 2) ? g_wv : g_wo;
    float4 v = ((const float4*)src)[i];
    ((uint2*)dst)[i] = make_uint2(pack_f16(v.x, v.y), pack_f16(v.z, v.w));
}

// ---------------------------------------------------------------------------
// GEMM: C[128x128 tile] = A[M,K] * B[N,K]^T, single fp16 pass.
// 256 threads, 8 warps (4x2 grid), warp tile 32x64 (round-10 geometry).
// K-chunks of 64, 3-stage cp.async pipeline (tail-aware); 2 CTAs/SM.
// OUT_MODE: 0 = fp32 C, 2 = fp16 (scaled by 'oscale').
// ---------------------------------------------------------------------------
#define GROWB 144
#define TILE_B (128 * GROWB)           // 18432
#define G_STAGE_B (2 * TILE_B)         // 36864: A, B
#define G_SMEM (3 * G_STAGE_B)         // 110592 -> 2 CTAs/SM = 216 KB

__device__ __forceinline__ void gemm_issue(
    uint32_t sbase, int buf, int tid,
    const unsigned short* __restrict__ A, const unsigned short* __restrict__ B,
    int rowBase, int colBase, int ch)
{
    const size_t kOff = (size_t)ch * 64;
    const uint32_t stage = sbase + buf * G_STAGE_B;
    const unsigned short* srcs[2] = {
        A + (size_t)rowBase * Dmodel + kOff,
        B + (size_t)colBase * Dmodel + kOff };
#pragma unroll
    for (int t = 0; t < 2; t++) {
        const unsigned short* src = srcs[t];
        const uint32_t dstT = stage + t * TILE_B;
#pragma unroll
        for (int it = 0; it < 4; it++) {
            int idx = it * 256 + tid;   // 0..1023
            int r = idx >> 3;
            int j = idx & 7;
            CP_ASYNC16(dstT + r * GROWB + j * 16, src + (size_t)r * Dmodel + j * 8);
        }
    }
    CP_COMMIT();
}

template<int OUT_MODE>
__device__ __forceinline__ void gemm_core(
    const unsigned short* __restrict__ A, const unsigned short* __restrict__ B,
    float* __restrict__ C, unsigned short* __restrict__ Cf, float oscale)
{
    extern __shared__ char smem[];
    const uint32_t sbase = smem_to_u32(smem);
    const int tid = threadIdx.x;
    const int wid = tid >> 5;
    const int lane = tid & 31;

    const int rowBase = blockIdx.y * 128;
    const int colBase = blockIdx.x * 128;
    const int m0 = (wid & 3) * 32;
    const int n0 = (wid >> 2) * 64;

    const int lr = (lane & 7) + (lane & 8);
    const int lk = (lane >> 4) << 3;

    float acc[2][8][4];
#pragma unroll
    for (int mt = 0; mt < 2; mt++)
#pragma unroll
        for (int nt = 0; nt < 8; nt++)
#pragma unroll
            for (int q = 0; q < 4; q++) acc[mt][nt][q] = 0.f;

    const int nch = Dmodel / 64;   // 32
    gemm_issue(sbase, 0, tid, A, B, rowBase, colBase, 0);
    gemm_issue(sbase, 1, tid, A, B, rowBase, colBase, 1);
    gemm_issue(sbase, 2, tid, A, B, rowBase, colBase, 2);

    int buf = 0;
    for (int ch = 0; ch < nch; ch++) {
        CP_WAIT_TAIL(ch, nch);
        __syncthreads();

        const uint32_t aB = sbase + buf * G_STAGE_B;
        const uint32_t bB = aB + TILE_B;

#pragma unroll
        for (int ks = 0; ks < 4; ks++) {
            const int k0 = ks * 16;
            uint32_t af[2][4];
#pragma unroll
            for (int mt = 0; mt < 2; mt++) {
                uint32_t off = (m0 + mt * 16 + lr) * GROWB + (k0 + lk) * 2;
                LDSM_X4(af[mt][0], af[mt][1], af[mt][2], af[mt][3], aB + off);
            }
            uint32_t bf[8][2];
#pragma unroll
            for (int jp = 0; jp < 4; jp++) {
                uint32_t off = (n0 + jp * 16 + lr) * GROWB + (k0 + lk) * 2;
                uint32_t r0, r1, r2, r3;
                LDSM_X4(r0, r1, r2, r3, bB + off);
                bf[2 * jp][0] = r0; bf[2 * jp][1] = r2;
                bf[2 * jp + 1][0] = r1; bf[2 * jp + 1][1] = r3;
            }
#pragma unroll
            for (int mt = 0; mt < 2; mt++)
#pragma unroll
                for (int nt = 0; nt < 8; nt++) MMA_F16(acc[mt][nt], af[mt], bf[nt]);
        }
        __syncthreads();
        if (ch + 3 < nch)
            gemm_issue(sbase, buf, tid, A, B, rowBase, colBase, ch + 3);
        buf = (buf == 2) ? 0 : buf + 1;
    }

    const int cr = lane >> 2;
    const int cc = (lane & 3) * 2;
#pragma unroll
    for (int mt = 0; mt < 2; mt++) {
#pragma unroll
        for (int nt = 0; nt < 8; nt++) {
            const int row = rowBase + m0 + mt * 16 + cr;
            const int col = colBase + n0 + nt * 8 + cc;
            if (OUT_MODE == 2) {
                *(uint32_t*)(Cf + (size_t)row * Dmodel + col) =
                    pack_f16(acc[mt][nt][0] * oscale, acc[mt][nt][1] * oscale);
                *(uint32_t*)(Cf + (size_t)(row + 8) * Dmodel + col) =
                    pack_f16(acc[mt][nt][2] * oscale, acc[mt][nt][3] * oscale);
            } else {
                *(float2*)&C[(size_t)row * Dmodel + col] = make_float2(acc[mt][nt][0], acc[mt][nt][1]);
                *(float2*)&C[(size_t)(row + 8) * Dmodel + col] = make_float2(acc[mt][nt][2], acc[mt][nt][3]);
            }
        }
    }
}

__global__ __launch_bounds__(256, 2) void gemm_qkv() {
    const int z = blockIdx.z;
    const unsigned short* B = (z == 0) ? g_wq : (z == 1) ? g_wk : g_wv;
    unsigned short* cf = (z == 0) ? g_qhi : (z == 1) ? g_khi : g_vhi;
    const float osc = (z == 0) ? (1.4426950408889634f * 0.08838834764831845f) : 1.0f;
    gemm_core<2>(g_xhi, B, nullptr, cf, osc);
}

__global__ __launch_bounds__(256, 2) void gemm_wo(float* __restrict__ out) {
    gemm_core<0>(g_yhi, g_wo, out, nullptr, 1.0f);
}

// ---------------------------------------------------------------------------
// Flash attention: 64-query CTAs, 128 threads (4 warps), 2 CTAs/SM.
// Q pre-scaled fp16; single-pass S and PV; 3-stage KV pipeline (tail-aware).
// (unchanged from round 12 — measured 156.7 us)
// ---------------------------------------------------------------------------
#define ASTRIDE 272
#define ATILE_B (64 * ASTRIDE)         // 17408
#define ASTAGE_B (2 * ATILE_B)         // 34816: K, V
#define ATTN_SMEM (3 * ASTAGE_B)       // 104448

__device__ __forceinline__ void attn_issue_kv(uint32_t sbase, int buf, int tid,
                                              size_t hbase, int kt)
{
    const unsigned short* srcs[2] = {g_khi, g_vhi};
    const uint32_t stage = sbase + buf * ASTAGE_B;
#pragma unroll
    for (int t = 0; t < 2; t++) {
        const unsigned short* src = srcs[t] + hbase + (size_t)(kt * 64) * Dmodel;
        const uint32_t dstT = stage + t * ATILE_B;
#pragma unroll
        for (int it = 0; it < 8; it++) {
            int idx = it * 128 + tid;
            int r = idx >> 4;
            int j = idx & 15;
            CP_ASYNC16(dstT + r * ASTRIDE + j * 16, src + (size_t)r * Dmodel + j * 8);
        }
    }
    CP_COMMIT();
}

__global__ __launch_bounds__(128, 2) void attn_mma()
{
    extern __shared__ char smem[];
    const uint32_t sbase = smem_to_u32(smem);
    const int tid = threadIdx.x;
    const int wid = tid >> 5;
    const int lane = tid & 31;

    const int qt = (gridDim.x - 1) - blockIdx.x;   // heavy tiles first
    const int h = blockIdx.y;
    const int b = blockIdx.z;
    const size_t hbase = ((size_t)b * Sseq) * Dmodel + (size_t)h * HDdim;

    const int lr = (lane & 7) + (lane & 8);
    const int lk = (lane >> 4) << 3;

    // stage Q (64 x 128 fp16, pre-scaled) through stage0 smem into frags
    {
#pragma unroll
        for (int it = 0; it < 8; it++) {
            int idx = it * 128 + tid;
            int r = idx >> 4;
            int j = idx & 15;
            const size_t goff = hbase + (size_t)(qt * 64 + r) * Dmodel + j * 8;
            CP_ASYNC16(sbase + r * ASTRIDE + j * 16, g_qhi + goff);
        }
        CP_COMMIT(); CP_WAIT0();
        __syncthreads();
    }
    uint32_t qf[8][4];
#pragma unroll
    for (int ks = 0; ks < 8; ks++) {
        uint32_t off = (wid * 16 + lr) * ASTRIDE + (ks * 16 + lk) * 2;
        LDSM_X4(qf[ks][0], qf[ks][1], qf[ks][2], qf[ks][3], sbase + off);
    }
    __syncthreads();

    float oacc[16][4];
#pragma unroll
    for (int nt = 0; nt < 16; nt++)
#pragma unroll
        for (int q = 0; q < 4; q++) oacc[nt][q] = 0.f;
    float m0 = -1e30f, m1 = -1e30f, l0 = 0.f, l1 = 0.f;

    const int nkt = qt + 1;
    attn_issue_kv(sbase, 0, tid, hbase, 0);
    if (nkt > 1) attn_issue_kv(sbase, 1, tid, hbase, 1);
    if (nkt > 2) attn_issue_kv(sbase, 2, tid, hbase, 2);

    const int row0 = qt * 64 + wid * 16 + (lane >> 2);

    int buf = 0;
    for (int kt = 0; kt < nkt; kt++) {
        CP_WAIT_TAIL(kt, nkt);
        __syncthreads();

        const uint32_t stage = sbase + buf * ASTAGE_B;
        const uint32_t kB = stage;
        const uint32_t vB = stage + ATILE_B;

        // S = Q K^T (Q pre-scaled; S already in log2 units)
        float sacc[8][4];
#pragma unroll
        for (int nt = 0; nt < 8; nt++)
#pragma unroll
            for (int q = 0; q < 4; q++) sacc[nt][q] = 0.f;
#pragma unroll
        for (int ks = 0; ks < 8; ks++) {
            uint32_t bh[8][2];
#pragma unroll
            for (int jp = 0; jp < 4; jp++) {
                uint32_t off = (jp * 16 + lr) * ASTRIDE + (ks * 16 + lk) * 2;
                uint32_t r0, r1, r2, r3;
                LDSM_X4(r0, r1, r2, r3, kB + off);
                bh[2 * jp][0] = r0; bh[2 * jp][1] = r2;
                bh[2 * jp + 1][0] = r1; bh[2 * jp + 1][1] = r3;
            }
#pragma unroll
            for (int nt = 0; nt < 8; nt++) MMA_F16(sacc[nt], qf[ks], bh[nt]);
        }

        // causal mask: only the diagonal k-tile needs it
        if (kt == qt) {
            const int col0 = kt * 64 + 2 * (lane & 3);
#pragma unroll
            for (int nt = 0; nt < 8; nt++) {
#pragma unroll
                for (int e = 0; e < 2; e++) {
                    if (col0 + nt * 8 + e > row0) sacc[nt][e] = -1e30f;
                    if (col0 + nt * 8 + e > row0 + 8) sacc[nt][2 + e] = -1e30f;
                }
            }
        }

        // online softmax in base-2
        float mx0 = -1e30f, mx1 = -1e30f;
#pragma unroll
        for (int nt = 0; nt < 8; nt++) {
            mx0 = fmaxf(mx0, fmaxf(sacc[nt][0], sacc[nt][1]));
            mx1 = fmaxf(mx1, fmaxf(sacc[nt][2], sacc[nt][3]));
        }
        mx0 = fmaxf(mx0, __shfl_xor_sync(0xffffffffu, mx0, 1));
        mx0 = fmaxf(mx0, __shfl_xor_sync(0xffffffffu, mx0, 2));
        mx1 = fmaxf(mx1, __shfl_xor_sync(0xffffffffu, mx1, 1));
        mx1 = fmaxf(mx1, __shfl_xor_sync(0xffffffffu, mx1, 2));
        float mn0 = fmaxf(m0, mx0), mn1 = fmaxf(m1, mx1);
        float a0 = fast_ex2(m0 - mn0), a1 = fast_ex2(m1 - mn1);
#pragma unroll
        for (int nt = 0; nt < 16; nt++) {
            oacc[nt][0] *= a0; oacc[nt][1] *= a0;
            oacc[nt][2] *= a1; oacc[nt][3] *= a1;
        }
        float ls0 = 0.f, ls1 = 0.f;
#pragma unroll
        for (int nt = 0; nt < 8; nt++) {
            float p0 = fast_ex2(sacc[nt][0] - mn0);
            float p1 = fast_ex2(sacc[nt][1] - mn0);
            float p2 = fast_ex2(sacc[nt][2] - mn1);
            float p3 = fast_ex2(sacc[nt][3] - mn1);
            sacc[nt][0] = p0; sacc[nt][1] = p1; sacc[nt][2] = p2; sacc[nt][3] = p3;
            ls0 += p0 + p1; ls1 += p2 + p3;
        }
        ls0 += __shfl_xor_sync(0xffffffffu, ls0, 1);
        ls0 += __shfl_xor_sync(0xffffffffu, ls0, 2);
        ls1 += __shfl_xor_sync(0xffffffffu, ls1, 1);
        ls1 += __shfl_xor_sync(0xffffffffu, ls1, 2);
        l0 = l0 * a0 + ls0; l1 = l1 * a1 + ls1;
        m0 = mn0; m1 = mn1;

        // O += P V, single fp16 pass
#pragma unroll
        for (int kstep = 0; kstep < 4; kstep++) {
            uint32_t ph[4];
            ph[0] = pack_f16(sacc[2 * kstep][0], sacc[2 * kstep][1]);
            ph[1] = pack_f16(sacc[2 * kstep][2], sacc[2 * kstep][3]);
            ph[2] = pack_f16(sacc[2 * kstep + 1][0], sacc[2 * kstep + 1][1]);
            ph[3] = pack_f16(sacc[2 * kstep + 1][2], sacc[2 * kstep + 1][3]);
#pragma unroll
            for (int db = 0; db < 2; db++) {
                uint32_t bv[8][2];
#pragma unroll
                for (int dpi = 0; dpi < 4; dpi++) {
                    const int dp = db * 4 + dpi;
                    uint32_t off = (kstep * 16 + lr) * ASTRIDE + (dp * 16 + lk) * 2;
                    uint32_t v0, v1, v2, v3;
                    LDSM_X4_T(v0, v1, v2, v3, vB + off);
                    bv[2 * dpi][0] = v0; bv[2 * dpi][1] = v1;
                    bv[2 * dpi + 1][0] = v2; bv[2 * dpi + 1][1] = v3;
                }
#pragma unroll
                for (int dpi = 0; dpi < 4; dpi++) {
                    MMA_F16(oacc[2 * (db * 4 + dpi)], ph, bv[2 * dpi]);
                    MMA_F16(oacc[2 * (db * 4 + dpi) + 1], ph, bv[2 * dpi + 1]);
                }
            }
        }

        __syncthreads();
        if (kt + 3 < nkt)
            attn_issue_kv(sbase, buf, tid, hbase, kt + 3);
        buf = (buf == 2) ? 0 : buf + 1;
    }

    const float inv0 = 1.f / l0;
    const float inv1 = 1.f / l1;
#pragma unroll
    for (int nt = 0; nt < 16; nt++) {
        const int col = nt * 8 + 2 * (lane & 3);
        const size_t i0 = ((size_t)b * Sseq + row0) * Dmodel + h * HDdim + col;
        const size_t i1 = ((size_t)b * Sseq + row0 + 8) * Dmodel + h * HDdim + col;
        *(uint32_t*)(g_yhi + i0) = pack_f16(oacc[nt][0] * inv0, oacc[nt][1] * inv0);
        *(uint32_t*)(g_yhi + i1) = pack_f16(oacc[nt][2] * inv1, oacc[nt][3] * inv1);
    }
}

// ---------------------------------------------------------------------------
// launch
// ---------------------------------------------------------------------------
extern "C" void kernel_launch(void* const* d_in, const int* in_sizes, int n_in,
                              void* d_out, int out_size)
{
    (void)in_sizes; (void)n_in; (void)out_size;
    const float* x  = (const float*)d_in[0];
    const float* Wq = (const float*)d_in[2];
    const float* Wk = (const float*)d_in[3];
    const float* Wv = (const float*)d_in[4];
    const float* Wo = (const float*)d_in[5];
    float* out = (float*)d_out;

    cudaFuncSetAttribute(gemm_qkv, cudaFuncAttributeMaxDynamicSharedMemorySize, G_SMEM);
    cudaFuncSetAttribute(gemm_wo, cudaFuncAttributeMaxDynamicSharedMemorySize, G_SMEM);
    cudaFuncSetAttribute(attn_mma, cudaFuncAttributeMaxDynamicSharedMemorySize, ATTN_SMEM);

    const int nX4 = Mrows * Dmodel / 4;
    const int nW4 = Dmodel * Dmodel / 4;

    conv_x<<<nX4 / 256, 256>>>(x);
    conv_w<<<dim3(nW4 / 256, 1, 4), 256>>>(Wq, Wk, Wv, Wo);

    gemm_qkv<<<dim3(Dmodel / 128, Mrows / 128, 3), 256, G_SMEM>>>();
    attn_mma<<<dim3(Sseq / 64, Hheads, Bsz), 128, ATTN_SMEM>>>();
    gemm_wo<<<dim3(Dmodel / 128, Mrows / 128, 1), 256, G_SMEM>>>(out);
}

// round 14
// speedup vs baseline: 1.0395x; 1.0016x over previous
#include <cuda_runtime.h>
#include <cuda_fp16.h>
#include <math.h>
#include <stdint.h>

#define Bsz 2
#define Sseq 2048
#define Dmodel 2048
#define Hheads 16
#define HDdim 128
#define Mrows (Bsz * Sseq)   // 4096

// ---------------- scratch (fp16 payloads in ushort arrays) ----------------
__device__ unsigned short g_xhi[Mrows * Dmodel];
__device__ unsigned short g_qhi[Mrows * Dmodel];
__device__ unsigned short g_khi[Mrows * Dmodel];
__device__ unsigned short g_vhi[Mrows * Dmodel];
__device__ unsigned short g_yhi[Mrows * Dmodel];
__device__ unsigned short g_wq[Dmodel * Dmodel];
__device__ unsigned short g_wk[Dmodel * Dmodel];
__device__ unsigned short g_wv[Dmodel * Dmodel];
__device__ unsigned short g_wo[Dmodel * Dmodel];

// ---------------- helpers ----------------
__device__ __forceinline__ uint32_t smem_to_u32(const void* p) {
    uint32_t a;
    asm("{ .reg .u64 t; cvta.to.shared.u64 t, %1; cvt.u32.u64 %0, t; }" : "=r"(a) : "l"(p));
    return a;
}

#define CP_ASYNC16(dst_u32, src_ptr) \
    asm volatile("cp.async.cg.shared.global [%0], [%1], 16;" :: "r"(dst_u32), "l"(src_ptr))
#define CP_COMMIT() asm volatile("cp.async.commit_group;")
#define CP_WAIT1()  asm volatile("cp.async.wait_group 1;")
#define CP_WAIT0()  asm volatile("cp.async.wait_group 0;")

#define LDSM_X4(r0, r1, r2, r3, addr) \
    asm volatile("ldmatrix.sync.aligned.m8n8.x4.shared.b16 {%0,%1,%2,%3}, [%4];" \
                 : "=r"(r0), "=r"(r1), "=r"(r2), "=r"(r3) : "r"(addr))
#define LDSM_X4_T(r0, r1, r2, r3, addr) \
    asm volatile("ldmatrix.sync.aligned.m8n8.x4.trans.shared.b16 {%0,%1,%2,%3}, [%4];" \
                 : "=r"(r0), "=r"(r1), "=r"(r2), "=r"(r3) : "r"(addr))

#define MMA_F16(c, a, b) \
    asm volatile("mma.sync.aligned.m16n8k16.row.col.f32.f16.f16.f32 " \
                 "{%0,%1,%2,%3},{%4,%5,%6,%7},{%8,%9},{%0,%1,%2,%3};" \
                 : "+f"((c)[0]), "+f"((c)[1]), "+f"((c)[2]), "+f"((c)[3]) \
                 : "r"((a)[0]), "r"((a)[1]), "r"((a)[2]), "r"((a)[3]), \
                   "r"((b)[0]), "r"((b)[1]))

__device__ __forceinline__ float fast_ex2(float x) {
    float y; asm("ex2.approx.f32 %0, %1;" : "=f"(y) : "f"(x)); return y;
}

__device__ __forceinline__ uint32_t pack_f16(float a, float b) {
    __half2 hv = __floats2half2_rn(a, b);
    return *reinterpret_cast<uint32_t*>(&hv);
}

// ---------------------------------------------------------------------------
// converts: fp32 -> fp16
// ---------------------------------------------------------------------------
__global__ __launch_bounds__(256) void conv_x(const float* __restrict__ x) {
    int i = blockIdx.x * blockDim.x + threadIdx.x;
    float4 v = ((const float4*)x)[i];
    ((uint2*)g_xhi)[i] = make_uint2(pack_f16(v.x, v.y), pack_f16(v.z, v.w));
}

__global__ __launch_bounds__(256) void conv_w(const float* __restrict__ Wq,
                                              const float* __restrict__ Wk,
                                              const float* __restrict__ Wv,
                                              const float* __restrict__ Wo) {
    int i = blockIdx.x * blockDim.x + threadIdx.x;
    int z = blockIdx.z;
    const float* src = (z == 0) ? Wq : (z == 1) ? Wk : (z == 2) ? Wv : Wo;
    unsigned short* dst = (z == 0) ? g_wq : (z == 1) ? g_wk : (z == 2) ? g_wv : g_wo;
    float4 v = ((const float4*)src)[i];
    ((uint2*)dst)[i] = make_uint2(pack_f16(v.x, v.y), pack_f16(v.z, v.w));
}

// ---------------------------------------------------------------------------
// GEMM: C[128x128 tile] = A[M,K] * B[N,K]^T, single fp16 pass.
// 256 threads, 8 warps (4x2), warp tile 32x64. K-chunks of 64.
// 3-buffer / single-barrier pipeline: issue for ch+2 right after the top
// barrier (writes the buffer freed at ch-1); wait_group 1 (0 at tail).
// OUT_MODE: 0 = fp32 C, 2 = fp16 (scaled by 'oscale').
// ---------------------------------------------------------------------------
#define GROWB 144
#define TILE_B (128 * GROWB)           // 18432
#define G_STAGE_B (2 * TILE_B)         // 36864: A, B
#define G_SMEM (3 * G_STAGE_B)         // 110592 -> 2 CTAs/SM

__device__ __forceinline__ void gemm_issue(
    uint32_t sbase, int buf, int tid,
    const unsigned short* __restrict__ A, const unsigned short* __restrict__ B,
    int rowBase, int colBase, int ch)
{
    const size_t kOff = (size_t)ch * 64;
    const uint32_t stage = sbase + buf * G_STAGE_B;
    const unsigned short* srcs[2] = {
        A + (size_t)rowBase * Dmodel + kOff,
        B + (size_t)colBase * Dmodel + kOff };
#pragma unroll
    for (int t = 0; t < 2; t++) {
        const unsigned short* src = srcs[t];
        const uint32_t dstT = stage + t * TILE_B;
#pragma unroll
        for (int it = 0; it < 4; it++) {
            int idx = it * 256 + tid;   // 0..1023
            int r = idx >> 3;
            int j = idx & 7;
            CP_ASYNC16(dstT + r * GROWB + j * 16, src + (size_t)r * Dmodel + j * 8);
        }
    }
    CP_COMMIT();
}

template<int OUT_MODE>
__device__ __forceinline__ void gemm_core(
    const unsigned short* __restrict__ A, const unsigned short* __restrict__ B,
    float* __restrict__ C, unsigned short* __restrict__ Cf, float oscale)
{
    extern __shared__ char smem[];
    const uint32_t sbase = smem_to_u32(smem);
    const int tid = threadIdx.x;
    const int wid = tid >> 5;
    const int lane = tid & 31;

    const int rowBase = blockIdx.y * 128;
    const int colBase = blockIdx.x * 128;
    const int m0 = (wid & 3) * 32;
    const int n0 = (wid >> 2) * 64;

    const int lr = (lane & 7) + (lane & 8);
    const int lk = (lane >> 4) << 3;

    float acc[2][8][4];
#pragma unroll
    for (int mt = 0; mt < 2; mt++)
#pragma unroll
        for (int nt = 0; nt < 8; nt++)
#pragma unroll
            for (int q = 0; q < 4; q++) acc[mt][nt][q] = 0.f;

    const int nch = Dmodel / 64;   // 32
    gemm_issue(sbase, 0, tid, A, B, rowBase, colBase, 0);
    gemm_issue(sbase, 1, tid, A, B, rowBase, colBase, 1);

    int buf = 0;
    for (int ch = 0; ch < nch; ch++) {
        if (ch + 1 < nch) { CP_WAIT1(); } else { CP_WAIT0(); }
        __syncthreads();

        // issue ch+2 into the buffer freed at iteration ch-1
        if (ch + 2 < nch) {
            int ibuf = buf + 2; if (ibuf >= 3) ibuf -= 3;
            gemm_issue(sbase, ibuf, tid, A, B, rowBase, colBase, ch + 2);
        }

        const uint32_t aB = sbase + buf * G_STAGE_B;
        const uint32_t bB = aB + TILE_B;

#pragma unroll
        for (int ks = 0; ks < 4; ks++) {
            const int k0 = ks * 16;
            uint32_t af[2][4];
#pragma unroll
            for (int mt = 0; mt < 2; mt++) {
                uint32_t off = (m0 + mt * 16 + lr) * GROWB + (k0 + lk) * 2;
                LDSM_X4(af[mt][0], af[mt][1], af[mt][2], af[mt][3], aB + off);
            }
            uint32_t bf[8][2];
#pragma unroll
            for (int jp = 0; jp < 4; jp++) {
                uint32_t off = (n0 + jp * 16 + lr) * GROWB + (k0 + lk) * 2;
                uint32_t r0, r1, r2, r3;
                LDSM_X4(r0, r1, r2, r3, bB + off);
                bf[2 * jp][0] = r0; bf[2 * jp][1] = r2;
                bf[2 * jp + 1][0] = r1; bf[2 * jp + 1][1] = r3;
            }
#pragma unroll
            for (int mt = 0; mt < 2; mt++)
#pragma unroll
                for (int nt = 0; nt < 8; nt++) MMA_F16(acc[mt][nt], af[mt], bf[nt]);
        }
        buf = (buf == 2) ? 0 : buf + 1;
    }

    const int cr = lane >> 2;
    const int cc = (lane & 3) * 2;
#pragma unroll
    for (int mt = 0; mt < 2; mt++) {
#pragma unroll
        for (int nt = 0; nt < 8; nt++) {
            const int row = rowBase + m0 + mt * 16 + cr;
            const int col = colBase + n0 + nt * 8 + cc;
            if (OUT_MODE == 2) {
                *(uint32_t*)(Cf + (size_t)row * Dmodel + col) =
                    pack_f16(acc[mt][nt][0] * oscale, acc[mt][nt][1] * oscale);
                *(uint32_t*)(Cf + (size_t)(row + 8) * Dmodel + col) =
                    pack_f16(acc[mt][nt][2] * oscale, acc[mt][nt][3] * oscale);
            } else {
                *(float2*)&C[(size_t)row * Dmodel + col] = make_float2(acc[mt][nt][0], acc[mt][nt][1]);
                *(float2*)&C[(size_t)(row + 8) * Dmodel + col] = make_float2(acc[mt][nt][2], acc[mt][nt][3]);
            }
        }
    }
}

__global__ __launch_bounds__(256, 2) void gemm_qkv() {
    const int z = blockIdx.z;
    const unsigned short* B = (z == 0) ? g_wq : (z == 1) ? g_wk : g_wv;
    unsigned short* cf = (z == 0) ? g_qhi : (z == 1) ? g_khi : g_vhi;
    const float osc = (z == 0) ? (1.4426950408889634f * 0.08838834764831845f) : 1.0f;
    gemm_core<2>(g_xhi, B, nullptr, cf, osc);
}

__global__ __launch_bounds__(256, 2) void gemm_wo(float* __restrict__ out) {
    gemm_core<0>(g_yhi, g_wo, out, nullptr, 1.0f);
}

// ---------------------------------------------------------------------------
// Flash attention: 64-query CTAs, 128 threads (4 warps), 2 CTAs/SM.
// Q pre-scaled fp16; single-pass S and PV; 3-buffer single-barrier pipeline.
// Row sums of P computed by an extra MMA against a constant all-ones B-frag
// (ones 16x8 fp16 B fragment == {0x3C003C00,0x3C003C00}) -> no FADD/shfl sums.
// ---------------------------------------------------------------------------
#define ASTRIDE 272
#define ATILE_B (64 * ASTRIDE)         // 17408
#define ASTAGE_B (2 * ATILE_B)         // 34816: K, V
#define ATTN_SMEM (3 * ASTAGE_B)       // 104448

__device__ __forceinline__ void attn_issue_kv(uint32_t sbase, int buf, int tid,
                                              size_t hbase, int kt)
{
    const unsigned short* srcs[2] = {g_khi, g_vhi};
    const uint32_t stage = sbase + buf * ASTAGE_B;
#pragma unroll
    for (int t = 0; t < 2; t++) {
        const unsigned short* src = srcs[t] + hbase + (size_t)(kt * 64) * Dmodel;
        const uint32_t dstT = stage + t * ATILE_B;
#pragma unroll
        for (int it = 0; it < 8; it++) {
            int idx = it * 128 + tid;
            int r = idx >> 4;
            int j = idx & 15;
            CP_ASYNC16(dstT + r * ASTRIDE + j * 16, src + (size_t)r * Dmodel + j * 8);
        }
    }
    CP_COMMIT();
}

__global__ __launch_bounds__(128, 2) void attn_mma()
{
    extern __shared__ char smem[];
    const uint32_t sbase = smem_to_u32(smem);
    const int tid = threadIdx.x;
    const int wid = tid >> 5;
    const int lane = tid & 31;

    const int qt = (gridDim.x - 1) - blockIdx.x;   // heavy tiles first
    const int h = blockIdx.y;
    const int b = blockIdx.z;
    const size_t hbase = ((size_t)b * Sseq) * Dmodel + (size_t)h * HDdim;

    const int lr = (lane & 7) + (lane & 8);
    const int lk = (lane >> 4) << 3;

    // stage Q (64 x 128 fp16, pre-scaled) through stage0 smem into frags
    {
#pragma unroll
        for (int it = 0; it < 8; it++) {
            int idx = it * 128 + tid;
            int r = idx >> 4;
            int j = idx & 15;
            const size_t goff = hbase + (size_t)(qt * 64 + r) * Dmodel + j * 8;
            CP_ASYNC16(sbase + r * ASTRIDE + j * 16, g_qhi + goff);
        }
        CP_COMMIT(); CP_WAIT0();
        __syncthreads();
    }
    uint32_t qf[8][4];
#pragma unroll
    for (int ks = 0; ks < 8; ks++) {
        uint32_t off = (wid * 16 + lr) * ASTRIDE + (ks * 16 + lk) * 2;
        LDSM_X4(qf[ks][0], qf[ks][1], qf[ks][2], qf[ks][3], sbase + off);
    }
    __syncthreads();

    float oacc[16][4];
#pragma unroll
    for (int nt = 0; nt < 16; nt++)
#pragma unroll
        for (int q = 0; q < 4; q++) oacc[nt][q] = 0.f;
    float lacc[4] = {0.f, 0.f, 0.f, 0.f};
    float m0 = -1e30f, m1 = -1e30f;

    const uint32_t onesf[2] = {0x3C003C00u, 0x3C003C00u};  // all-ones fp16 B-frag

    const int nkt = qt + 1;
    attn_issue_kv(sbase, 0, tid, hbase, 0);
    if (nkt > 1) attn_issue_kv(sbase, 1, tid, hbase, 1);

    const int row0 = qt * 64 + wid * 16 + (lane >> 2);

    int buf = 0;
    for (int kt = 0; kt < nkt; kt++) {
        if (kt + 1 < nkt) { CP_WAIT1(); } else { CP_WAIT0(); }
        __syncthreads();

        // issue kt+2 into the buffer freed at iteration kt-1
        if (kt + 2 < nkt) {
            int ibuf = buf + 2; if (ibuf >= 3) ibuf -= 3;
            attn_issue_kv(sbase, ibuf, tid, hbase, kt + 2);
        }

        const uint32_t stage = sbase + buf * ASTAGE_B;
        const uint32_t kB = stage;
        const uint32_t vB = stage + ATILE_B;

        // S = Q K^T (Q pre-scaled; S already in log2 units)
        float sacc[8][4];
#pragma unroll
        for (int nt = 0; nt < 8; nt++)
#pragma unroll
            for (int q = 0; q < 4; q++) sacc[nt][q] = 0.f;
#pragma unroll
        for (int ks = 0; ks < 8; ks++) {
            uint32_t bh[8][2];
#pragma unroll
            for (int jp = 0; jp < 4; jp++) {
                uint32_t off = (jp * 16 + lr) * ASTRIDE + (ks * 16 + lk) * 2;
                uint32_t r0, r1, r2, r3;
                LDSM_X4(r0, r1, r2, r3, kB + off);
                bh[2 * jp][0] = r0; bh[2 * jp][1] = r2;
                bh[2 * jp + 1][0] = r1; bh[2 * jp + 1][1] = r3;
            }
#pragma unroll
            for (int nt = 0; nt < 8; nt++) MMA_F16(sacc[nt], qf[ks], bh[nt]);
        }

        // causal mask: only the diagonal k-tile needs it
        if (kt == qt) {
            const int col0 = kt * 64 + 2 * (lane & 3);
#pragma unroll
            for (int nt = 0; nt < 8; nt++) {
#pragma unroll
                for (int e = 0; e < 2; e++) {
                    if (col0 + nt * 8 + e > row0) sacc[nt][e] = -1e30f;
                    if (col0 + nt * 8 + e > row0 + 8) sacc[nt][2 + e] = -1e30f;
                }
            }
        }

        // online softmax in base-2 (row sums deferred to the ones-MMA)
        float mx0 = -1e30f, mx1 = -1e30f;
#pragma unroll
        for (int nt = 0; nt < 8; nt++) {
            mx0 = fmaxf(mx0, fmaxf(sacc[nt][0], sacc[nt][1]));
            mx1 = fmaxf(mx1, fmaxf(sacc[nt][2], sacc[nt][3]));
        }
        mx0 = fmaxf(mx0, __shfl_xor_sync(0xffffffffu, mx0, 1));
        mx0 = fmaxf(mx0, __shfl_xor_sync(0xffffffffu, mx0, 2));
        mx1 = fmaxf(mx1, __shfl_xor_sync(0xffffffffu, mx1, 1));
        mx1 = fmaxf(mx1, __shfl_xor_sync(0xffffffffu, mx1, 2));
        float mn0 = fmaxf(m0, mx0), mn1 = fmaxf(m1, mx1);
        float a0 = fast_ex2(m0 - mn0), a1 = fast_ex2(m1 - mn1);
#pragma unroll
        for (int nt = 0; nt < 16; nt++) {
            oacc[nt][0] *= a0; oacc[nt][1] *= a0;
            oacc[nt][2] *= a1; oacc[nt][3] *= a1;
        }
        lacc[0] *= a0; lacc[1] *= a0; lacc[2] *= a1; lacc[3] *= a1;
#pragma unroll
        for (int nt = 0; nt < 8; nt++) {
            sacc[nt][0] = fast_ex2(sacc[nt][0] - mn0);
            sacc[nt][1] = fast_ex2(sacc[nt][1] - mn0);
            sacc[nt][2] = fast_ex2(sacc[nt][2] - mn1);
            sacc[nt][3] = fast_ex2(sacc[nt][3] - mn1);
        }
        m0 = mn0; m1 = mn1;

        // O += P V (single fp16 pass); l += P * ones via constant B-frag
#pragma unroll
        for (int kstep = 0; kstep < 4; kstep++) {
            uint32_t ph[4];
            ph[0] = pack_f16(sacc[2 * kstep][0], sacc[2 * kstep][1]);
            ph[1] = pack_f16(sacc[2 * kstep][2], sacc[2 * kstep][3]);
            ph[2] = pack_f16(sacc[2 * kstep + 1][0], sacc[2 * kstep + 1][1]);
            ph[3] = pack_f16(sacc[2 * kstep + 1][2], sacc[2 * kstep + 1][3]);
            MMA_F16(lacc, ph, onesf);
#pragma unroll
            for (int db = 0; db < 2; db++) {
                uint32_t bv[8][2];
#pragma unroll
                for (int dpi = 0; dpi < 4; dpi++) {
                    const int dp = db * 4 + dpi;
                    uint32_t off = (kstep * 16 + lr) * ASTRIDE + (dp * 16 + lk) * 2;
                    uint32_t v0, v1, v2, v3;
                    LDSM_X4_T(v0, v1, v2, v3, vB + off);
                    bv[2 * dpi][0] = v0; bv[2 * dpi][1] = v1;
                    bv[2 * dpi + 1][0] = v2; bv[2 * dpi + 1][1] = v3;
                }
#pragma unroll
                for (int dpi = 0; dpi < 4; dpi++) {
                    MMA_F16(oacc[2 * (db * 4 + dpi)], ph, bv[2 * dpi]);
                    MMA_F16(oacc[2 * (db * 4 + dpi) + 1], ph, bv[2 * dpi + 1]);
                }
            }
        }

        buf = (buf == 2) ? 0 : buf + 1;
    }

    const float inv0 = 1.f / lacc[0];
    const float inv1 = 1.f / lacc[2];
#pragma unroll
    for (int nt = 0; nt < 16; nt++) {
        const int col = nt * 8 + 2 * (lane & 3);
        const size_t i0 = ((size_t)b * Sseq + row0) * Dmodel + h * HDdim + col;
        const size_t i1 = ((size_t)b * Sseq + row0 + 8) * Dmodel + h * HDdim + col;
        *(uint32_t*)(g_yhi + i0) = pack_f16(oacc[nt][0] * inv0, oacc[nt][1] * inv0);
        *(uint32_t*)(g_yhi + i1) = pack_f16(oacc[nt][2] * inv1, oacc[nt][3] * inv1);
    }
}

// ---------------------------------------------------------------------------
// launch
// ---------------------------------------------------------------------------
extern "C" void kernel_launch(void* const* d_in, const int* in_sizes, int n_in,
                              void* d_out, int out_size)
{
    (void)in_sizes; (void)n_in; (void)out_size;
    const float* x  = (const float*)d_in[0];
    const float* Wq = (const float*)d_in[2];
    const float* Wk = (const float*)d_in[3];
    const float* Wv = (const float*)d_in[4];
    const float* Wo = (const float*)d_in[5];
    float* out = (float*)d_out;

    cudaFuncSetAttribute(gemm_qkv, cudaFuncAttributeMaxDynamicSharedMemorySize, G_SMEM);
    cudaFuncSetAttribute(gemm_wo, cudaFuncAttributeMaxDynamicSharedMemorySize, G_SMEM);
    cudaFuncSetAttribute(attn_mma, cudaFuncAttributeMaxDynamicSharedMemorySize, ATTN_SMEM);

    const int nX4 = Mrows * Dmodel / 4;
    const int nW4 = Dmodel * Dmodel / 4;

    conv_x<<<nX4 / 256, 256>>>(x);
    conv_w<<<dim3(nW4 / 256, 1, 4), 256>>>(Wq, Wk, Wv, Wo);

    gemm_qkv<<<dim3(Dmodel / 128, Mrows / 128, 3), 256, G_SMEM>>>();
    attn_mma<<<dim3(Sseq / 64, Hheads, Bsz), 128, ATTN_SMEM>>>();
    gemm_wo<<<dim3(Dmodel / 128, Mrows / 128, 1), 256, G_SMEM>>>(out);
}

// round 15
// speedup vs baseline: 1.0465x; 1.0067x over previous
#include <cuda_runtime.h>
#include <cuda_fp16.h>
#include <math.h>
#include <stdint.h>

#define Bsz 2
#define Sseq 2048
#define Dmodel 2048
#define Hheads 16
#define HDdim 128
#define Mrows (Bsz * Sseq)   // 4096

// ---------------- scratch (fp16 payloads in ushort arrays) ----------------
__device__ unsigned short g_xhi[Mrows * Dmodel];
__device__ unsigned short g_qhi[Mrows * Dmodel];
__device__ unsigned short g_khi[Mrows * Dmodel];
__device__ unsigned short g_vhi[Mrows * Dmodel];
__device__ unsigned short g_yhi[Mrows * Dmodel];
__device__ unsigned short g_wq[Dmodel * Dmodel];
__device__ unsigned short g_wk[Dmodel * Dmodel];
__device__ unsigned short g_wv[Dmodel * Dmodel];
__device__ unsigned short g_wo[Dmodel * Dmodel];

// ---------------- helpers ----------------
__device__ __forceinline__ uint32_t smem_to_u32(const void* p) {
    uint32_t a;
    asm("{ .reg .u64 t; cvta.to.shared.u64 t, %1; cvt.u32.u64 %0, t; }" : "=r"(a) : "l"(p));
    return a;
}

#define CP_ASYNC16(dst_u32, src_ptr) \
    asm volatile("cp.async.cg.shared.global [%0], [%1], 16;" :: "r"(dst_u32), "l"(src_ptr))
#define CP_COMMIT() asm volatile("cp.async.commit_group;")
#define CP_WAIT1()  asm volatile("cp.async.wait_group 1;")
#define CP_WAIT0()  asm volatile("cp.async.wait_group 0;")

#define LDSM_X4(r0, r1, r2, r3, addr) \
    asm volatile("ldmatrix.sync.aligned.m8n8.x4.shared.b16 {%0,%1,%2,%3}, [%4];" \
                 : "=r"(r0), "=r"(r1), "=r"(r2), "=r"(r3) : "r"(addr))
#define LDSM_X4_T(r0, r1, r2, r3, addr) \
    asm volatile("ldmatrix.sync.aligned.m8n8.x4.trans.shared.b16 {%0,%1,%2,%3}, [%4];" \
                 : "=r"(r0), "=r"(r1), "=r"(r2), "=r"(r3) : "r"(addr))

#define MMA_F16(c, a, b) \
    asm volatile("mma.sync.aligned.m16n8k16.row.col.f32.f16.f16.f32 " \
                 "{%0,%1,%2,%3},{%4,%5,%6,%7},{%8,%9},{%0,%1,%2,%3};" \
                 : "+f"((c)[0]), "+f"((c)[1]), "+f"((c)[2]), "+f"((c)[3]) \
                 : "r"((a)[0]), "r"((a)[1]), "r"((a)[2]), "r"((a)[3]), \
                   "r"((b)[0]), "r"((b)[1]))

__device__ __forceinline__ float fast_ex2(float x) {
    float y; asm("ex2.approx.f32 %0, %1;" : "=f"(y) : "f"(x)); return y;
}

__device__ __forceinline__ uint32_t pack_f16(float a, float b) {
    __half2 hv = __floats2half2_rn(a, b);
    return *reinterpret_cast<uint32_t*>(&hv);
}

// ---------------------------------------------------------------------------
// converts: fp32 -> fp16
// ---------------------------------------------------------------------------
__global__ __launch_bounds__(256) void conv_x(const float* __restrict__ x) {
    int i = blockIdx.x * blockDim.x + threadIdx.x;
    float4 v = ((const float4*)x)[i];
    ((uint2*)g_xhi)[i] = make_uint2(pack_f16(v.x, v.y), pack_f16(v.z, v.w));
}

__global__ __launch_bounds__(256) void conv_w(const float* __restrict__ Wq,
                                              const float* __restrict__ Wk,
                                              const float* __restrict__ Wv,
                                              const float* __restrict__ Wo) {
    int i = blockIdx.x * blockDim.x + threadIdx.x;
    int z = blockIdx.z;
    const float* src = (z == 0) ? Wq : (z == 1) ? Wk : (z == 2) ? Wv : Wo;
    unsigned short* dst = (z == 0) ? g_wq : (z == 1) ? g_wk : (z == 2) ? g_wv : g_wo;
    float4 v = ((const float4*)src)[i];
    ((uint2*)dst)[i] = make_uint2(pack_f16(v.x, v.y), pack_f16(v.z, v.w));
}

// ---------------------------------------------------------------------------
// GEMM: C[128x128 tile] = A[M,K] * B[N,K]^T, single fp16 pass.
// 256 threads, 8 warps (4x2), warp tile 32x64. K-chunks of 64.
// 3-buffer / single-barrier pipeline. 2 CTAs/SM. (unchanged from round 14)
// ---------------------------------------------------------------------------
#define GROWB 144
#define TILE_B (128 * GROWB)           // 18432
#define G_STAGE_B (2 * TILE_B)         // 36864: A, B
#define G_SMEM (3 * G_STAGE_B)         // 110592

__device__ __forceinline__ void gemm_issue(
    uint32_t sbase, int buf, int tid,
    const unsigned short* __restrict__ A, const unsigned short* __restrict__ B,
    int rowBase, int colBase, int ch)
{
    const size_t kOff = (size_t)ch * 64;
    const uint32_t stage = sbase + buf * G_STAGE_B;
    const unsigned short* srcs[2] = {
        A + (size_t)rowBase * Dmodel + kOff,
        B + (size_t)colBase * Dmodel + kOff };
#pragma unroll
    for (int t = 0; t < 2; t++) {
        const unsigned short* src = srcs[t];
        const uint32_t dstT = stage + t * TILE_B;
#pragma unroll
        for (int it = 0; it < 4; it++) {
            int idx = it * 256 + tid;
            int r = idx >> 3;
            int j = idx & 7;
            CP_ASYNC16(dstT + r * GROWB + j * 16, src + (size_t)r * Dmodel + j * 8);
        }
    }
    CP_COMMIT();
}

template<int OUT_MODE>
__device__ __forceinline__ void gemm_core(
    const unsigned short* __restrict__ A, const unsigned short* __restrict__ B,
    float* __restrict__ C, unsigned short* __restrict__ Cf, float oscale)
{
    extern __shared__ char smem[];
    const uint32_t sbase = smem_to_u32(smem);
    const int tid = threadIdx.x;
    const int wid = tid >> 5;
    const int lane = tid & 31;

    const int rowBase = blockIdx.y * 128;
    const int colBase = blockIdx.x * 128;
    const int m0 = (wid & 3) * 32;
    const int n0 = (wid >> 2) * 64;

    const int lr = (lane & 7) + (lane & 8);
    const int lk = (lane >> 4) << 3;

    float acc[2][8][4];
#pragma unroll
    for (int mt = 0; mt < 2; mt++)
#pragma unroll
        for (int nt = 0; nt < 8; nt++)
#pragma unroll
            for (int q = 0; q < 4; q++) acc[mt][nt][q] = 0.f;

    const int nch = Dmodel / 64;   // 32
    gemm_issue(sbase, 0, tid, A, B, rowBase, colBase, 0);
    gemm_issue(sbase, 1, tid, A, B, rowBase, colBase, 1);

    int buf = 0;
    for (int ch = 0; ch < nch; ch++) {
        if (ch + 1 < nch) { CP_WAIT1(); } else { CP_WAIT0(); }
        __syncthreads();

        if (ch + 2 < nch) {
            int ibuf = buf + 2; if (ibuf >= 3) ibuf -= 3;
            gemm_issue(sbase, ibuf, tid, A, B, rowBase, colBase, ch + 2);
        }

        const uint32_t aB = sbase + buf * G_STAGE_B;
        const uint32_t bB = aB + TILE_B;

#pragma unroll
        for (int ks = 0; ks < 4; ks++) {
            const int k0 = ks * 16;
            uint32_t af[2][4];
#pragma unroll
            for (int mt = 0; mt < 2; mt++) {
                uint32_t off = (m0 + mt * 16 + lr) * GROWB + (k0 + lk) * 2;
                LDSM_X4(af[mt][0], af[mt][1], af[mt][2], af[mt][3], aB + off);
            }
            uint32_t bf[8][2];
#pragma unroll
            for (int jp = 0; jp < 4; jp++) {
                uint32_t off = (n0 + jp * 16 + lr) * GROWB + (k0 + lk) * 2;
                uint32_t r0, r1, r2, r3;
                LDSM_X4(r0, r1, r2, r3, bB + off);
                bf[2 * jp][0] = r0; bf[2 * jp][1] = r2;
                bf[2 * jp + 1][0] = r1; bf[2 * jp + 1][1] = r3;
            }
#pragma unroll
            for (int mt = 0; mt < 2; mt++)
#pragma unroll
                for (int nt = 0; nt < 8; nt++) MMA_F16(acc[mt][nt], af[mt], bf[nt]);
        }
        buf = (buf == 2) ? 0 : buf + 1;
    }

    const int cr = lane >> 2;
    const int cc = (lane & 3) * 2;
#pragma unroll
    for (int mt = 0; mt < 2; mt++) {
#pragma unroll
        for (int nt = 0; nt < 8; nt++) {
            const int row = rowBase + m0 + mt * 16 + cr;
            const int col = colBase + n0 + nt * 8 + cc;
            if (OUT_MODE == 2) {
                *(uint32_t*)(Cf + (size_t)row * Dmodel + col) =
                    pack_f16(acc[mt][nt][0] * oscale, acc[mt][nt][1] * oscale);
                *(uint32_t*)(Cf + (size_t)(row + 8) * Dmodel + col) =
                    pack_f16(acc[mt][nt][2] * oscale, acc[mt][nt][3] * oscale);
            } else {
                *(float2*)&C[(size_t)row * Dmodel + col] = make_float2(acc[mt][nt][0], acc[mt][nt][1]);
                *(float2*)&C[(size_t)(row + 8) * Dmodel + col] = make_float2(acc[mt][nt][2], acc[mt][nt][3]);
            }
        }
    }
}

__global__ __launch_bounds__(256, 2) void gemm_qkv() {
    const int z = blockIdx.z;
    const unsigned short* B = (z == 0) ? g_wq : (z == 1) ? g_wk : g_wv;
    unsigned short* cf = (z == 0) ? g_qhi : (z == 1) ? g_khi : g_vhi;
    const float osc = (z == 0) ? (1.4426950408889634f * 0.08838834764831845f) : 1.0f;
    gemm_core<2>(g_xhi, B, nullptr, cf, osc);
}

__global__ __launch_bounds__(256, 2) void gemm_wo(float* __restrict__ out) {
    gemm_core<0>(g_yhi, g_wo, out, nullptr, 1.0f);
}

// ---------------------------------------------------------------------------
// Flash attention: 64-query CTAs, 128 threads (4 warps), TARGET 3 CTAs/SM.
// 2-stage / 2-barrier KV pipeline (69.6 KB smem). Q pre-scaled fp16;
// single-pass S and PV; l-sums via ones-MMA.
// ---------------------------------------------------------------------------
#define ASTRIDE 272
#define ATILE_B (64 * ASTRIDE)         // 17408
#define ASTAGE_B (2 * ATILE_B)         // 34816: K, V
#define ATTN_SMEM (2 * ASTAGE_B)       // 69632 -> 3 CTAs/SM

__device__ __forceinline__ void attn_issue_kv(uint32_t sbase, int buf, int tid,
                                              size_t hbase, int kt)
{
    const unsigned short* srcs[2] = {g_khi, g_vhi};
    const uint32_t stage = sbase + buf * ASTAGE_B;
#pragma unroll
    for (int t = 0; t < 2; t++) {
        const unsigned short* src = srcs[t] + hbase + (size_t)(kt * 64) * Dmodel;
        const uint32_t dstT = stage + t * ATILE_B;
#pragma unroll
        for (int it = 0; it < 8; it++) {
            int idx = it * 128 + tid;
            int r = idx >> 4;
            int j = idx & 15;
            CP_ASYNC16(dstT + r * ASTRIDE + j * 16, src + (size_t)r * Dmodel + j * 8);
        }
    }
    CP_COMMIT();
}

__global__ __launch_bounds__(128, 3) void attn_mma()
{
    extern __shared__ char smem[];
    const uint32_t sbase = smem_to_u32(smem);
    const int tid = threadIdx.x;
    const int wid = tid >> 5;
    const int lane = tid & 31;

    const int qt = (gridDim.x - 1) - blockIdx.x;   // heavy tiles first
    const int h = blockIdx.y;
    const int b = blockIdx.z;
    const size_t hbase = ((size_t)b * Sseq) * Dmodel + (size_t)h * HDdim;

    const int lr = (lane & 7) + (lane & 8);
    const int lk = (lane >> 4) << 3;

    // stage Q (64 x 128 fp16, pre-scaled) through stage0 smem into frags
    {
#pragma unroll
        for (int it = 0; it < 8; it++) {
            int idx = it * 128 + tid;
            int r = idx >> 4;
            int j = idx & 15;
            const size_t goff = hbase + (size_t)(qt * 64 + r) * Dmodel + j * 8;
            CP_ASYNC16(sbase + r * ASTRIDE + j * 16, g_qhi + goff);
        }
        CP_COMMIT(); CP_WAIT0();
        __syncthreads();
    }
    uint32_t qf[8][4];
#pragma unroll
    for (int ks = 0; ks < 8; ks++) {
        uint32_t off = (wid * 16 + lr) * ASTRIDE + (ks * 16 + lk) * 2;
        LDSM_X4(qf[ks][0], qf[ks][1], qf[ks][2], qf[ks][3], sbase + off);
    }
    __syncthreads();

    float oacc[16][4];
#pragma unroll
    for (int nt = 0; nt < 16; nt++)
#pragma unroll
        for (int q = 0; q < 4; q++) oacc[nt][q] = 0.f;
    float lacc[4] = {0.f, 0.f, 0.f, 0.f};
    float m0 = -1e30f, m1 = -1e30f;

    const uint32_t onesf[2] = {0x3C003C00u, 0x3C003C00u};  // all-ones fp16 B-frag

    const int nkt = qt + 1;
    attn_issue_kv(sbase, 0, tid, hbase, 0);
    if (nkt > 1) attn_issue_kv(sbase, 1, tid, hbase, 1);

    const int row0 = qt * 64 + wid * 16 + (lane >> 2);

    for (int kt = 0; kt < nkt; kt++) {
        if (kt + 1 < nkt) { CP_WAIT1(); } else { CP_WAIT0(); }
        __syncthreads();

        const uint32_t stage = sbase + (kt & 1) * ASTAGE_B;
        const uint32_t kB = stage;
        const uint32_t vB = stage + ATILE_B;

        // S = Q K^T
        float sacc[8][4];
#pragma unroll
        for (int nt = 0; nt < 8; nt++)
#pragma unroll
            for (int q = 0; q < 4; q++) sacc[nt][q] = 0.f;
#pragma unroll
        for (int ks = 0; ks < 8; ks++) {
            uint32_t bh[8][2];
#pragma unroll
            for (int jp = 0; jp < 4; jp++) {
                uint32_t off = (jp * 16 + lr) * ASTRIDE + (ks * 16 + lk) * 2;
                uint32_t r0, r1, r2, r3;
                LDSM_X4(r0, r1, r2, r3, kB + off);
                bh[2 * jp][0] = r0; bh[2 * jp][1] = r2;
                bh[2 * jp + 1][0] = r1; bh[2 * jp + 1][1] = r3;
            }
#pragma unroll
            for (int nt = 0; nt < 8; nt++) MMA_F16(sacc[nt], qf[ks], bh[nt]);
        }

        // causal mask: only the diagonal k-tile needs it
        if (kt == qt) {
            const int col0 = kt * 64 + 2 * (lane & 3);
#pragma unroll
            for (int nt = 0; nt < 8; nt++) {
#pragma unroll
                for (int e = 0; e < 2; e++) {
                    if (col0 + nt * 8 + e > row0) sacc[nt][e] = -1e30f;
                    if (col0 + nt * 8 + e > row0 + 8) sacc[nt][2 + e] = -1e30f;
                }
            }
        }

        // online softmax in base-2 (row sums via ones-MMA)
        float mx0 = -1e30f, mx1 = -1e30f;
#pragma unroll
        for (int nt = 0; nt < 8; nt++) {
            mx0 = fmaxf(mx0, fmaxf(sacc[nt][0], sacc[nt][1]));
            mx1 = fmaxf(mx1, fmaxf(sacc[nt][2], sacc[nt][3]));
        }
        mx0 = fmaxf(mx0, __shfl_xor_sync(0xffffffffu, mx0, 1));
        mx0 = fmaxf(mx0, __shfl_xor_sync(0xffffffffu, mx0, 2));
        mx1 = fmaxf(mx1, __shfl_xor_sync(0xffffffffu, mx1, 1));
        mx1 = fmaxf(mx1, __shfl_xor_sync(0xffffffffu, mx1, 2));
        float mn0 = fmaxf(m0, mx0), mn1 = fmaxf(m1, mx1);
        float a0 = fast_ex2(m0 - mn0), a1 = fast_ex2(m1 - mn1);
#pragma unroll
        for (int nt = 0; nt < 16; nt++) {
            oacc[nt][0] *= a0; oacc[nt][1] *= a0;
            oacc[nt][2] *= a1; oacc[nt][3] *= a1;
        }
        lacc[0] *= a0; lacc[1] *= a0; lacc[2] *= a1; lacc[3] *= a1;
#pragma unroll
        for (int nt = 0; nt < 8; nt++) {
            sacc[nt][0] = fast_ex2(sacc[nt][0] - mn0);
            sacc[nt][1] = fast_ex2(sacc[nt][1] - mn0);
            sacc[nt][2] = fast_ex2(sacc[nt][2] - mn1);
            sacc[nt][3] = fast_ex2(sacc[nt][3] - mn1);
        }
        m0 = mn0; m1 = mn1;

        // O += P V; l += P * ones
#pragma unroll
        for (int kstep = 0; kstep < 4; kstep++) {
            uint32_t ph[4];
            ph[0] = pack_f16(sacc[2 * kstep][0], sacc[2 * kstep][1]);
            ph[1] = pack_f16(sacc[2 * kstep][2], sacc[2 * kstep][3]);
            ph[2] = pack_f16(sacc[2 * kstep + 1][0], sacc[2 * kstep + 1][1]);
            ph[3] = pack_f16(sacc[2 * kstep + 1][2], sacc[2 * kstep + 1][3]);
            MMA_F16(lacc, ph, onesf);
#pragma unroll
            for (int db = 0; db < 2; db++) {
                uint32_t bv[8][2];
#pragma unroll
                for (int dpi = 0; dpi < 4; dpi++) {
                    const int dp = db * 4 + dpi;
                    uint32_t off = (kstep * 16 + lr) * ASTRIDE + (dp * 16 + lk) * 2;
                    uint32_t v0, v1, v2, v3;
                    LDSM_X4_T(v0, v1, v2, v3, vB + off);
                    bv[2 * dpi][0] = v0; bv[2 * dpi][1] = v1;
                    bv[2 * dpi + 1][0] = v2; bv[2 * dpi + 1][1] = v3;
                }
#pragma unroll
                for (int dpi = 0; dpi < 4; dpi++) {
                    MMA_F16(oacc[2 * (db * 4 + dpi)], ph, bv[2 * dpi]);
                    MMA_F16(oacc[2 * (db * 4 + dpi) + 1], ph, bv[2 * dpi + 1]);
                }
            }
        }

        __syncthreads();
        if (kt + 2 < nkt)
            attn_issue_kv(sbase, kt & 1, tid, hbase, kt + 2);
    }

    const float inv0 = 1.f / lacc[0];
    const float inv1 = 1.f / lacc[2];
#pragma unroll
    for (int nt = 0; nt < 16; nt++) {
        const int col = nt * 8 + 2 * (lane & 3);
        const size_t i0 = ((size_t)b * Sseq + row0) * Dmodel + h * HDdim + col;
        const size_t i1 = ((size_t)b * Sseq + row0 + 8) * Dmodel + h * HDdim + col;
        *(uint32_t*)(g_yhi + i0) = pack_f16(oacc[nt][0] * inv0, oacc[nt][1] * inv0);
        *(uint32_t*)(g_yhi + i1) = pack_f16(oacc[nt][2] * inv1, oacc[nt][3] * inv1);
    }
}

// ---------------------------------------------------------------------------
// launch
// ---------------------------------------------------------------------------
extern "C" void kernel_launch(void* const* d_in, const int* in_sizes, int n_in,
                              void* d_out, int out_size)
{
    (void)in_sizes; (void)n_in; (void)out_size;
    const float* x  = (const float*)d_in[0];
    const float* Wq = (const float*)d_in[2];
    const float* Wk = (const float*)d_in[3];
    const float* Wv = (const float*)d_in[4];
    const float* Wo = (const float*)d_in[5];
    float* out = (float*)d_out;

    cudaFuncSetAttribute(gemm_qkv, cudaFuncAttributeMaxDynamicSharedMemorySize, G_SMEM);
    cudaFuncSetAttribute(gemm_wo, cudaFuncAttributeMaxDynamicSharedMemorySize, G_SMEM);
    cudaFuncSetAttribute(attn_mma, cudaFuncAttributeMaxDynamicSharedMemorySize, ATTN_SMEM);

    const int nX4 = Mrows * Dmodel / 4;
    const int nW4 = Dmodel * Dmodel / 4;

    conv_x<<<nX4 / 256, 256>>>(x);
    conv_w<<<dim3(nW4 / 256, 1, 4), 256>>>(Wq, Wk, Wv, Wo);

    gemm_qkv<<<dim3(Dmodel / 128, Mrows / 128, 3), 256, G_SMEM>>>();
    attn_mma<<<dim3(Sseq / 64, Hheads, Bsz), 128, ATTN_SMEM>>>();
    gemm_wo<<<dim3(Dmodel / 128, Mrows / 128, 1), 256, G_SMEM>>>(out);
}

// round 16
// speedup vs baseline: 1.0535x; 1.0067x over previous
#include <cuda_runtime.h>
#include <cuda_fp16.h>
#include <math.h>
#include <stdint.h>

#define Bsz 2
#define Sseq 2048
#define Dmodel 2048
#define Hheads 16
#define HDdim 128
#define Mrows (Bsz * Sseq)   // 4096

// ---------------- scratch (fp16 payloads in ushort arrays) ----------------
__device__ unsigned short g_xhi[Mrows * Dmodel];
__device__ unsigned short g_qhi[Mrows * Dmodel];
__device__ unsigned short g_khi[Mrows * Dmodel];
__device__ unsigned short g_vhi[Mrows * Dmodel];
__device__ unsigned short g_yhi[Mrows * Dmodel];
__device__ unsigned short g_wq[Dmodel * Dmodel];
__device__ unsigned short g_wk[Dmodel * Dmodel];
__device__ unsigned short g_wv[Dmodel * Dmodel];
__device__ unsigned short g_wo[Dmodel * Dmodel];

// ---------------- helpers ----------------
__device__ __forceinline__ uint32_t smem_to_u32(const void* p) {
    uint32_t a;
    asm("{ .reg .u64 t; cvta.to.shared.u64 t, %1; cvt.u32.u64 %0, t; }" : "=r"(a) : "l"(p));
    return a;
}

#define CP_ASYNC16(dst_u32, src_ptr) \
    asm volatile("cp.async.cg.shared.global [%0], [%1], 16;" :: "r"(dst_u32), "l"(src_ptr))
#define CP_COMMIT() asm volatile("cp.async.commit_group;")
#define CP_WAIT1()  asm volatile("cp.async.wait_group 1;")
#define CP_WAIT0()  asm volatile("cp.async.wait_group 0;")

#define LDSM_X4(r0, r1, r2, r3, addr) \
    asm volatile("ldmatrix.sync.aligned.m8n8.x4.shared.b16 {%0,%1,%2,%3}, [%4];" \
                 : "=r"(r0), "=r"(r1), "=r"(r2), "=r"(r3) : "r"(addr))
#define LDSM_X4_T(r0, r1, r2, r3, addr) \
    asm volatile("ldmatrix.sync.aligned.m8n8.x4.trans.shared.b16 {%0,%1,%2,%3}, [%4];" \
                 : "=r"(r0), "=r"(r1), "=r"(r2), "=r"(r3) : "r"(addr))

// fp32-accumulator MMA (rt~16)
#define MMA_F16(c, a, b) \
    asm volatile("mma.sync.aligned.m16n8k16.row.col.f32.f16.f16.f32 " \
                 "{%0,%1,%2,%3},{%4,%5,%6,%7},{%8,%9},{%0,%1,%2,%3};" \
                 : "+f"((c)[0]), "+f"((c)[1]), "+f"((c)[2]), "+f"((c)[3]) \
                 : "r"((a)[0]), "r"((a)[1]), "r"((a)[2]), "r"((a)[3]), \
                   "r"((b)[0]), "r"((b)[1]))

// fp16-accumulator MMA (rt~8) — used only for S = QK^T
#define MMA_F16_H(c, a, b) \
    asm volatile("mma.sync.aligned.m16n8k16.row.col.f16.f16.f16.f16 " \
                 "{%0,%1},{%2,%3,%4,%5},{%6,%7},{%0,%1};" \
                 : "+r"((c)[0]), "+r"((c)[1]) \
                 : "r"((a)[0]), "r"((a)[1]), "r"((a)[2]), "r"((a)[3]), \
                   "r"((b)[0]), "r"((b)[1]))

__device__ __forceinline__ float fast_ex2(float x) {
    float y; asm("ex2.approx.f32 %0, %1;" : "=f"(y) : "f"(x)); return y;
}

__device__ __forceinline__ uint32_t pack_f16(float a, float b) {
    __half2 hv = __floats2half2_rn(a, b);
    return *reinterpret_cast<uint32_t*>(&hv);
}
__device__ __forceinline__ uint32_t hmax2u(uint32_t a, uint32_t b) {
    __half2 r = __hmax2(*reinterpret_cast<__half2*>(&a), *reinterpret_cast<__half2*>(&b));
    return *reinterpret_cast<uint32_t*>(&r);
}
__device__ __forceinline__ uint32_t h2exp2_sub(uint32_t s, uint32_t m) {
    __half2 d = __hsub2(*reinterpret_cast<__half2*>(&s), *reinterpret_cast<__half2*>(&m));
    __half2 r = h2exp2(d);
    return *reinterpret_cast<uint32_t*>(&r);
}

// ---------------------------------------------------------------------------
// converts: fp32 -> fp16
// ---------------------------------------------------------------------------
__global__ __launch_bounds__(256) void conv_x(const float* __restrict__ x) {
    int i = blockIdx.x * blockDim.x + threadIdx.x;
    float4 v = ((const float4*)x)[i];
    ((uint2*)g_xhi)[i] = make_uint2(pack_f16(v.x, v.y), pack_f16(v.z, v.w));
}

__global__ __launch_bounds__(256) void conv_w(const float* __restrict__ Wq,
                                              const float* __restrict__ Wk,
                                              const float* __restrict__ Wv,
                                              const float* __restrict__ Wo) {
    int i = blockIdx.x * blockDim.x + threadIdx.x;
    int z = blockIdx.z;
    const float* src = (z == 0) ? Wq : (z == 1) ? Wk : (z == 2) ? Wv : Wo;
    unsigned short* dst = (z == 0) ? g_wq : (z == 1) ? g_wk : (z == 2) ? g_wv : g_wo;
    float4 v = ((const float4*)src)[i];
    ((uint2*)dst)[i] = make_uint2(pack_f16(v.x, v.y), pack_f16(v.z, v.w));
}

// ---------------------------------------------------------------------------
// GEMM: unchanged from round 15 (at the fp32-acc tensor floor).
// ---------------------------------------------------------------------------
#define GROWB 144
#define TILE_B (128 * GROWB)           // 18432
#define G_STAGE_B (2 * TILE_B)         // 36864: A, B
#define G_SMEM (3 * G_STAGE_B)         // 110592

__device__ __forceinline__ void gemm_issue(
    uint32_t sbase, int buf, int tid,
    const unsigned short* __restrict__ A, const unsigned short* __restrict__ B,
    int rowBase, int colBase, int ch)
{
    const size_t kOff = (size_t)ch * 64;
    const uint32_t stage = sbase + buf * G_STAGE_B;
    const unsigned short* srcs[2] = {
        A + (size_t)rowBase * Dmodel + kOff,
        B + (size_t)colBase * Dmodel + kOff };
#pragma unroll
    for (int t = 0; t < 2; t++) {
        const unsigned short* src = srcs[t];
        const uint32_t dstT = stage + t * TILE_B;
#pragma unroll
        for (int it = 0; it < 4; it++) {
            int idx = it * 256 + tid;
            int r = idx >> 3;
            int j = idx & 7;
            CP_ASYNC16(dstT + r * GROWB + j * 16, src + (size_t)r * Dmodel + j * 8);
        }
    }
    CP_COMMIT();
}

template<int OUT_MODE>
__device__ __forceinline__ void gemm_core(
    const unsigned short* __restrict__ A, const unsigned short* __restrict__ B,
    float* __restrict__ C, unsigned short* __restrict__ Cf, float oscale)
{
    extern __shared__ char smem[];
    const uint32_t sbase = smem_to_u32(smem);
    const int tid = threadIdx.x;
    const int wid = tid >> 5;
    const int lane = tid & 31;

    const int rowBase = blockIdx.y * 128;
    const int colBase = blockIdx.x * 128;
    const int m0 = (wid & 3) * 32;
    const int n0 = (wid >> 2) * 64;

    const int lr = (lane & 7) + (lane & 8);
    const int lk = (lane >> 4) << 3;

    float acc[2][8][4];
#pragma unroll
    for (int mt = 0; mt < 2; mt++)
#pragma unroll
        for (int nt = 0; nt < 8; nt++)
#pragma unroll
            for (int q = 0; q < 4; q++) acc[mt][nt][q] = 0.f;

    const int nch = Dmodel / 64;   // 32
    gemm_issue(sbase, 0, tid, A, B, rowBase, colBase, 0);
    gemm_issue(sbase, 1, tid, A, B, rowBase, colBase, 1);

    int buf = 0;
    for (int ch = 0; ch < nch; ch++) {
        if (ch + 1 < nch) { CP_WAIT1(); } else { CP_WAIT0(); }
        __syncthreads();

        if (ch + 2 < nch) {
            int ibuf = buf + 2; if (ibuf >= 3) ibuf -= 3;
            gemm_issue(sbase, ibuf, tid, A, B, rowBase, colBase, ch + 2);
        }

        const uint32_t aB = sbase + buf * G_STAGE_B;
        const uint32_t bB = aB + TILE_B;

#pragma unroll
        for (int ks = 0; ks < 4; ks++) {
            const int k0 = ks * 16;
            uint32_t af[2][4];
#pragma unroll
            for (int mt = 0; mt < 2; mt++) {
                uint32_t off = (m0 + mt * 16 + lr) * GROWB + (k0 + lk) * 2;
                LDSM_X4(af[mt][0], af[mt][1], af[mt][2], af[mt][3], aB + off);
            }
            uint32_t bf[8][2];
#pragma unroll
            for (int jp = 0; jp < 4; jp++) {
                uint32_t off = (n0 + jp * 16 + lr) * GROWB + (k0 + lk) * 2;
                uint32_t r0, r1, r2, r3;
                LDSM_X4(r0, r1, r2, r3, bB + off);
                bf[2 * jp][0] = r0; bf[2 * jp][1] = r2;
                bf[2 * jp + 1][0] = r1; bf[2 * jp + 1][1] = r3;
            }
#pragma unroll
            for (int mt = 0; mt < 2; mt++)
#pragma unroll
                for (int nt = 0; nt < 8; nt++) MMA_F16(acc[mt][nt], af[mt], bf[nt]);
        }
        buf = (buf == 2) ? 0 : buf + 1;
    }

    const int cr = lane >> 2;
    const int cc = (lane & 3) * 2;
#pragma unroll
    for (int mt = 0; mt < 2; mt++) {
#pragma unroll
        for (int nt = 0; nt < 8; nt++) {
            const int row = rowBase + m0 + mt * 16 + cr;
            const int col = colBase + n0 + nt * 8 + cc;
            if (OUT_MODE == 2) {
                *(uint32_t*)(Cf + (size_t)row * Dmodel + col) =
                    pack_f16(acc[mt][nt][0] * oscale, acc[mt][nt][1] * oscale);
                *(uint32_t*)(Cf + (size_t)(row + 8) * Dmodel + col) =
                    pack_f16(acc[mt][nt][2] * oscale, acc[mt][nt][3] * oscale);
            } else {
                *(float2*)&C[(size_t)row * Dmodel + col] = make_float2(acc[mt][nt][0], acc[mt][nt][1]);
                *(float2*)&C[(size_t)(row + 8) * Dmodel + col] = make_float2(acc[mt][nt][2], acc[mt][nt][3]);
            }
        }
    }
}

__global__ __launch_bounds__(256, 2) void gemm_qkv() {
    const int z = blockIdx.z;
    const unsigned short* B = (z == 0) ? g_wq : (z == 1) ? g_wk : g_wv;
    unsigned short* cf = (z == 0) ? g_qhi : (z == 1) ? g_khi : g_vhi;
    const float osc = (z == 0) ? (1.4426950408889634f * 0.08838834764831845f) : 1.0f;
    gemm_core<2>(g_xhi, B, nullptr, cf, osc);
}

__global__ __launch_bounds__(256, 2) void gemm_wo(float* __restrict__ out) {
    gemm_core<0>(g_yhi, g_wo, out, nullptr, 1.0f);
}

// ---------------------------------------------------------------------------
// Flash attention: 64-query CTAs, 128 threads (4 warps), 3 CTAs/SM.
// S = QK^T in fp16-accumulator MMA (rt8); softmax in f16x2 (h2exp2, hmax2);
// PV + l-sum (ones-MMA) in fp32-acc. 2-stage KV pipeline.
// ---------------------------------------------------------------------------
#define ASTRIDE 272
#define ATILE_B (64 * ASTRIDE)         // 17408
#define ASTAGE_B (2 * ATILE_B)         // 34816: K, V
#define ATTN_SMEM (2 * ASTAGE_B)       // 69632 -> 3 CTAs/SM

__device__ __forceinline__ void attn_issue_kv(uint32_t sbase, int buf, int tid,
                                              size_t hbase, int kt)
{
    const unsigned short* srcs[2] = {g_khi, g_vhi};
    const uint32_t stage = sbase + buf * ASTAGE_B;
#pragma unroll
    for (int t = 0; t < 2; t++) {
        const unsigned short* src = srcs[t] + hbase + (size_t)(kt * 64) * Dmodel;
        const uint32_t dstT = stage + t * ATILE_B;
#pragma unroll
        for (int it = 0; it < 8; it++) {
            int idx = it * 128 + tid;
            int r = idx >> 4;
            int j = idx & 15;
            CP_ASYNC16(dstT + r * ASTRIDE + j * 16, src + (size_t)r * Dmodel + j * 8);
        }
    }
    CP_COMMIT();
}

__global__ __launch_bounds__(128, 3) void attn_mma()
{
    extern __shared__ char smem[];
    const uint32_t sbase = smem_to_u32(smem);
    const int tid = threadIdx.x;
    const int wid = tid >> 5;
    const int lane = tid & 31;

    const int qt = (gridDim.x - 1) - blockIdx.x;   // heavy tiles first
    const int h = blockIdx.y;
    const int b = blockIdx.z;
    const size_t hbase = ((size_t)b * Sseq) * Dmodel + (size_t)h * HDdim;

    const int lr = (lane & 7) + (lane & 8);
    const int lk = (lane >> 4) << 3;

    // stage Q (64 x 128 fp16, pre-scaled) through stage0 smem into frags
    {
#pragma unroll
        for (int it = 0; it < 8; it++) {
            int idx = it * 128 + tid;
            int r = idx >> 4;
            int j = idx & 15;
            const size_t goff = hbase + (size_t)(qt * 64 + r) * Dmodel + j * 8;
            CP_ASYNC16(sbase + r * ASTRIDE + j * 16, g_qhi + goff);
        }
        CP_COMMIT(); CP_WAIT0();
        __syncthreads();
    }
    uint32_t qf[8][4];
#pragma unroll
    for (int ks = 0; ks < 8; ks++) {
        uint32_t off = (wid * 16 + lr) * ASTRIDE + (ks * 16 + lk) * 2;
        LDSM_X4(qf[ks][0], qf[ks][1], qf[ks][2], qf[ks][3], sbase + off);
    }
    __syncthreads();

    float oacc[16][4];
#pragma unroll
    for (int nt = 0; nt < 16; nt++)
#pragma unroll
        for (int q = 0; q < 4; q++) oacc[nt][q] = 0.f;
    float lacc[4] = {0.f, 0.f, 0.f, 0.f};
    float m0 = -1e30f, m1 = -1e30f;

    const uint32_t onesf[2] = {0x3C003C00u, 0x3C003C00u};  // all-ones fp16 B-frag

    const int nkt = qt + 1;
    attn_issue_kv(sbase, 0, tid, hbase, 0);
    if (nkt > 1) attn_issue_kv(sbase, 1, tid, hbase, 1);

    const int row0 = qt * 64 + wid * 16 + (lane >> 2);

    for (int kt = 0; kt < nkt; kt++) {
        if (kt + 1 < nkt) { CP_WAIT1(); } else { CP_WAIT0(); }
        __syncthreads();

        const uint32_t stage = sbase + (kt & 1) * ASTAGE_B;
        const uint32_t kB = stage;
        const uint32_t vB = stage + ATILE_B;

        // S = Q K^T in fp16-acc (reg0 = row r cols c,c+1; reg1 = row r+8)
        uint32_t sacc[8][2];
#pragma unroll
        for (int nt = 0; nt < 8; nt++) { sacc[nt][0] = 0u; sacc[nt][1] = 0u; }
#pragma unroll
        for (int ks = 0; ks < 8; ks++) {
            uint32_t bh[8][2];
#pragma unroll
            for (int jp = 0; jp < 4; jp++) {
                uint32_t off = (jp * 16 + lr) * ASTRIDE + (ks * 16 + lk) * 2;
                uint32_t r0, r1, r2, r3;
                LDSM_X4(r0, r1, r2, r3, kB + off);
                bh[2 * jp][0] = r0; bh[2 * jp][1] = r2;
                bh[2 * jp + 1][0] = r1; bh[2 * jp + 1][1] = r3;
            }
#pragma unroll
            for (int nt = 0; nt < 8; nt++) MMA_F16_H(sacc[nt], qf[ks], bh[nt]);
        }

        // causal mask on the diagonal k-tile (fp16 -inf = 0xFC00)
        if (kt == qt) {
            const int colA = kt * 64 + 2 * (lane & 3);
#pragma unroll
            for (int nt = 0; nt < 8; nt++) {
                const int c = colA + nt * 8;
                uint32_t w0 = sacc[nt][0], w1 = sacc[nt][1];
                if (c > row0)     w0 = (w0 & 0xFFFF0000u) | 0x0000FC00u;
                if (c + 1 > row0) w0 = (w0 & 0x0000FFFFu) | 0xFC000000u;
                if (c > row0 + 8)     w1 = (w1 & 0xFFFF0000u) | 0x0000FC00u;
                if (c + 1 > row0 + 8) w1 = (w1 & 0x0000FFFFu) | 0xFC000000u;
                sacc[nt][0] = w0; sacc[nt][1] = w1;
            }
        }

        // row max in f16x2
        uint32_t ux0 = 0xFC00FC00u, ux1 = 0xFC00FC00u;
#pragma unroll
        for (int nt = 0; nt < 8; nt++) {
            ux0 = hmax2u(ux0, sacc[nt][0]);
            ux1 = hmax2u(ux1, sacc[nt][1]);
        }
        {
            __half2 t0 = *reinterpret_cast<__half2*>(&ux0);
            t0 = __hmax2(t0, __lowhigh2highlow(t0));
            ux0 = *reinterpret_cast<uint32_t*>(&t0);
            __half2 t1 = *reinterpret_cast<__half2*>(&ux1);
            t1 = __hmax2(t1, __lowhigh2highlow(t1));
            ux1 = *reinterpret_cast<uint32_t*>(&t1);
        }
        ux0 = hmax2u(ux0, __shfl_xor_sync(0xffffffffu, ux0, 1));
        ux0 = hmax2u(ux0, __shfl_xor_sync(0xffffffffu, ux0, 2));
        ux1 = hmax2u(ux1, __shfl_xor_sync(0xffffffffu, ux1, 1));
        ux1 = hmax2u(ux1, __shfl_xor_sync(0xffffffffu, ux1, 2));
        float mx0 = __half2float(__low2half(*reinterpret_cast<__half2*>(&ux0)));
        float mx1 = __half2float(__low2half(*reinterpret_cast<__half2*>(&ux1)));

        float mn0 = fmaxf(m0, mx0), mn1 = fmaxf(m1, mx1);
        float a0 = fast_ex2(m0 - mn0), a1 = fast_ex2(m1 - mn1);
#pragma unroll
        for (int nt = 0; nt < 16; nt++) {
            oacc[nt][0] *= a0; oacc[nt][1] *= a0;
            oacc[nt][2] *= a1; oacc[nt][3] *= a1;
        }
        lacc[0] *= a0; lacc[1] *= a0; lacc[2] *= a1; lacc[3] *= a1;
        m0 = mn0; m1 = mn1;

        __half2 mh0 = __float2half2_rn(mn0);
        __half2 mh1 = __float2half2_rn(mn1);
        const uint32_t mu0 = *reinterpret_cast<uint32_t*>(&mh0);
        const uint32_t mu1 = *reinterpret_cast<uint32_t*>(&mh1);

        // O += P V; l += P * ones. p = 2^(s-m) directly in f16x2.
#pragma unroll
        for (int kstep = 0; kstep < 4; kstep++) {
            uint32_t ph[4];
            ph[0] = h2exp2_sub(sacc[2 * kstep][0], mu0);
            ph[1] = h2exp2_sub(sacc[2 * kstep][1], mu1);
            ph[2] = h2exp2_sub(sacc[2 * kstep + 1][0], mu0);
            ph[3] = h2exp2_sub(sacc[2 * kstep + 1][1], mu1);
            MMA_F16(lacc, ph, onesf);
#pragma unroll
            for (int db = 0; db < 2; db++) {
                uint32_t bv[8][2];
#pragma unroll
                for (int dpi = 0; dpi < 4; dpi++) {
                    const int dp = db * 4 + dpi;
                    uint32_t off = (kstep * 16 + lr) * ASTRIDE + (dp * 16 + lk) * 2;
                    uint32_t v0, v1, v2, v3;
                    LDSM_X4_T(v0, v1, v2, v3, vB + off);
                    bv[2 * dpi][0] = v0; bv[2 * dpi][1] = v1;
                    bv[2 * dpi + 1][0] = v2; bv[2 * dpi + 1][1] = v3;
                }
#pragma unroll
                for (int dpi = 0; dpi < 4; dpi++) {
                    MMA_F16(oacc[2 * (db * 4 + dpi)], ph, bv[2 * dpi]);
                    MMA_F16(oacc[2 * (db * 4 + dpi) + 1], ph, bv[2 * dpi + 1]);
                }
            }
        }

        __syncthreads();
        if (kt + 2 < nkt)
            attn_issue_kv(sbase, kt & 1, tid, hbase, kt + 2);
    }

    const float inv0 = 1.f / lacc[0];
    const float inv1 = 1.f / lacc[2];
#pragma unroll
    for (int nt = 0; nt < 16; nt++) {
        const int col = nt * 8 + 2 * (lane & 3);
        const size_t i0 = ((size_t)b * Sseq + row0) * Dmodel + h * HDdim + col;
        const size_t i1 = ((size_t)b * Sseq + row0 + 8) * Dmodel + h * HDdim + col;
        *(uint32_t*)(g_yhi + i0) = pack_f16(oacc[nt][0] * inv0, oacc[nt][1] * inv0);
        *(uint32_t*)(g_yhi + i1) = pack_f16(oacc[nt][2] * inv1, oacc[nt][3] * inv1);
    }
}

// ---------------------------------------------------------------------------
// launch
// ---------------------------------------------------------------------------
extern "C" void kernel_launch(void* const* d_in, const int* in_sizes, int n_in,
                              void* d_out, int out_size)
{
    (void)in_sizes; (void)n_in; (void)out_size;
    const float* x  = (const float*)d_in[0];
    const float* Wq = (const float*)d_in[2];
    const float* Wk = (const float*)d_in[3];
    const float* Wv = (const float*)d_in[4];
    const float* Wo = (const float*)d_in[5];
    float* out = (float*)d_out;

    cudaFuncSetAttribute(gemm_qkv, cudaFuncAttributeMaxDynamicSharedMemorySize, G_SMEM);
    cudaFuncSetAttribute(gemm_wo, cudaFuncAttributeMaxDynamicSharedMemorySize, G_SMEM);
    cudaFuncSetAttribute(attn_mma, cudaFuncAttributeMaxDynamicSharedMemorySize, ATTN_SMEM);

    const int nX4 = Mrows * Dmodel / 4;
    const int nW4 = Dmodel * Dmodel / 4;

    conv_x<<<nX4 / 256, 256>>>(x);
    conv_w<<<dim3(nW4 / 256, 1, 4), 256>>>(Wq, Wk, Wv, Wo);

    gemm_qkv<<<dim3(Dmodel / 128, Mrows / 128, 3), 256, G_SMEM>>>();
    attn_mma<<<dim3(Sseq / 64, Hheads, Bsz), 128, ATTN_SMEM>>>();
    gemm_wo<<<dim3(Dmodel / 128, Mrows / 128, 1), 256, G_SMEM>>>(out);
}

// round 17
// speedup vs baseline: 1.0658x; 1.0117x over previous
#include <cuda_runtime.h>
#include <cuda_fp16.h>
#include <math.h>
#include <stdint.h>

#define Bsz 2
#define Sseq 2048
#define Dmodel 2048
#define Hheads 16
#define HDdim 128
#define Mrows (Bsz * Sseq)   // 4096

// ---------------- scratch (fp16 payloads in ushort arrays) ----------------
__device__ unsigned short g_xhi[Mrows * Dmodel];
__device__ unsigned short g_qhi[Mrows * Dmodel];
__device__ unsigned short g_khi[Mrows * Dmodel];
__device__ unsigned short g_vhi[Mrows * Dmodel];
__device__ unsigned short g_yhi[Mrows * Dmodel];
__device__ unsigned short g_wq[Dmodel * Dmodel];
__device__ unsigned short g_wk[Dmodel * Dmodel];
__device__ unsigned short g_wv[Dmodel * Dmodel];
__device__ unsigned short g_wo[Dmodel * Dmodel];

// ---------------- helpers ----------------
__device__ __forceinline__ uint32_t smem_to_u32(const void* p) {
    uint32_t a;
    asm("{ .reg .u64 t; cvta.to.shared.u64 t, %1; cvt.u32.u64 %0, t; }" : "=r"(a) : "l"(p));
    return a;
}

#define CP_ASYNC16(dst_u32, src_ptr) \
    asm volatile("cp.async.cg.shared.global [%0], [%1], 16;" :: "r"(dst_u32), "l"(src_ptr))
#define CP_COMMIT() asm volatile("cp.async.commit_group;")
#define CP_WAIT1()  asm volatile("cp.async.wait_group 1;")
#define CP_WAIT0()  asm volatile("cp.async.wait_group 0;")

#define LDSM_X4(r0, r1, r2, r3, addr) \
    asm volatile("ldmatrix.sync.aligned.m8n8.x4.shared.b16 {%0,%1,%2,%3}, [%4];" \
                 : "=r"(r0), "=r"(r1), "=r"(r2), "=r"(r3) : "r"(addr))
#define LDSM_X4_T(r0, r1, r2, r3, addr) \
    asm volatile("ldmatrix.sync.aligned.m8n8.x4.trans.shared.b16 {%0,%1,%2,%3}, [%4];" \
                 : "=r"(r0), "=r"(r1), "=r"(r2), "=r"(r3) : "r"(addr))

// fp32-accumulator MMA (rt~16)
#define MMA_F16(c, a, b) \
    asm volatile("mma.sync.aligned.m16n8k16.row.col.f32.f16.f16.f32 " \
                 "{%0,%1,%2,%3},{%4,%5,%6,%7},{%8,%9},{%0,%1,%2,%3};" \
                 : "+f"((c)[0]), "+f"((c)[1]), "+f"((c)[2]), "+f"((c)[3]) \
                 : "r"((a)[0]), "r"((a)[1]), "r"((a)[2]), "r"((a)[3]), \
                   "r"((b)[0]), "r"((b)[1]))

// fp16-accumulator MMA (rt~8) — used only for S = QK^T
#define MMA_F16_H(c, a, b) \
    asm volatile("mma.sync.aligned.m16n8k16.row.col.f16.f16.f16.f16 " \
                 "{%0,%1},{%2,%3,%4,%5},{%6,%7},{%0,%1};" \
                 : "+r"((c)[0]), "+r"((c)[1]) \
                 : "r"((a)[0]), "r"((a)[1]), "r"((a)[2]), "r"((a)[3]), \
                   "r"((b)[0]), "r"((b)[1]))

__device__ __forceinline__ float fast_ex2(float x) {
    float y; asm("ex2.approx.f32 %0, %1;" : "=f"(y) : "f"(x)); return y;
}

__device__ __forceinline__ uint32_t pack_f16(float a, float b) {
    __half2 hv = __floats2half2_rn(a, b);
    return *reinterpret_cast<uint32_t*>(&hv);
}
__device__ __forceinline__ uint32_t hmax2u(uint32_t a, uint32_t b) {
    __half2 r = __hmax2(*reinterpret_cast<__half2*>(&a), *reinterpret_cast<__half2*>(&b));
    return *reinterpret_cast<uint32_t*>(&r);
}
__device__ __forceinline__ uint32_t h2exp2_sub(uint32_t s, uint32_t m) {
    __half2 d = __hsub2(*reinterpret_cast<__half2*>(&s), *reinterpret_cast<__half2*>(&m));
    __half2 r = h2exp2(d);
    return *reinterpret_cast<uint32_t*>(&r);
}

// ---------------------------------------------------------------------------
// fused convert: fp32 -> fp16 for x + all 4 weights in ONE launch.
// Each thread produces 4 uint4 outputs (8 LDG.128 in flight -> high MLP).
// Bit-identical results to the previous conv_x / conv_w kernels.
// ---------------------------------------------------------------------------
#define CONV_OUT4_X (Mrows * Dmodel / 8)     // 1M uint4 outputs for x
#define CONV_OUT4_W (Dmodel * Dmodel / 8)    // 512K per weight

__global__ __launch_bounds__(256) void conv_all(const float* __restrict__ x,
                                                const float* __restrict__ Wq,
                                                const float* __restrict__ Wk,
                                                const float* __restrict__ Wv,
                                                const float* __restrict__ Wo)
{
    const int z = blockIdx.z;
    const float* src = (z == 0) ? x : (z == 1) ? Wq : (z == 2) ? Wk : (z == 3) ? Wv : Wo;
    unsigned short* dst = (z == 0) ? g_xhi : (z == 1) ? g_wq : (z == 2) ? g_wk
                        : (z == 3) ? g_wv : g_wo;
    const int nOut = (z == 0) ? CONV_OUT4_X : CONV_OUT4_W;

    const float4* in4 = (const float4*)src;
    uint4* out4 = (uint4*)dst;

#pragma unroll
    for (int it = 0; it < 4; it++) {
        int o = blockIdx.x * 1024 + it * 256 + threadIdx.x;
        if (o < nOut) {
            float4 a = in4[2 * o];
            float4 b = in4[2 * o + 1];
            uint4 r;
            r.x = pack_f16(a.x, a.y);
            r.y = pack_f16(a.z, a.w);
            r.z = pack_f16(b.x, b.y);
            r.w = pack_f16(b.z, b.w);
            out4[o] = r;
        }
    }
}

// ---------------------------------------------------------------------------
// GEMM: unchanged from round 16 (at the fp32-acc tensor floor).
// ---------------------------------------------------------------------------
#define GROWB 144
#define TILE_B (128 * GROWB)           // 18432
#define G_STAGE_B (2 * TILE_B)         // 36864: A, B
#define G_SMEM (3 * G_STAGE_B)         // 110592

__device__ __forceinline__ void gemm_issue(
    uint32_t sbase, int buf, int tid,
    const unsigned short* __restrict__ A, const unsigned short* __restrict__ B,
    int rowBase, int colBase, int ch)
{
    const size_t kOff = (size_t)ch * 64;
    const uint32_t stage = sbase + buf * G_STAGE_B;
    const unsigned short* srcs[2] = {
        A + (size_t)rowBase * Dmodel + kOff,
        B + (size_t)colBase * Dmodel + kOff };
#pragma unroll
    for (int t = 0; t < 2; t++) {
        const unsigned short* src = srcs[t];
        const uint32_t dstT = stage + t * TILE_B;
#pragma unroll
        for (int it = 0; it < 4; it++) {
            int idx = it * 256 + tid;
            int r = idx >> 3;
            int j = idx & 7;
            CP_ASYNC16(dstT + r * GROWB + j * 16, src + (size_t)r * Dmodel + j * 8);
        }
    }
    CP_COMMIT();
}

template<int OUT_MODE>
__device__ __forceinline__ void gemm_core(
    const unsigned short* __restrict__ A, const unsigned short* __restrict__ B,
    float* __restrict__ C, unsigned short* __restrict__ Cf, float oscale)
{
    extern __shared__ char smem[];
    const uint32_t sbase = smem_to_u32(smem);
    const int tid = threadIdx.x;
    const int wid = tid >> 5;
    const int lane = tid & 31;

    const int rowBase = blockIdx.y * 128;
    const int colBase = blockIdx.x * 128;
    const int m0 = (wid & 3) * 32;
    const int n0 = (wid >> 2) * 64;

    const int lr = (lane & 7) + (lane & 8);
    const int lk = (lane >> 4) << 3;

    float acc[2][8][4];
#pragma unroll
    for (int mt = 0; mt < 2; mt++)
#pragma unroll
        for (int nt = 0; nt < 8; nt++)
#pragma unroll
            for (int q = 0; q < 4; q++) acc[mt][nt][q] = 0.f;

    const int nch = Dmodel / 64;   // 32
    gemm_issue(sbase, 0, tid, A, B, rowBase, colBase, 0);
    gemm_issue(sbase, 1, tid, A, B, rowBase, colBase, 1);

    int buf = 0;
    for (int ch = 0; ch < nch; ch++) {
        if (ch + 1 < nch) { CP_WAIT1(); } else { CP_WAIT0(); }
        __syncthreads();

        if (ch + 2 < nch) {
            int ibuf = buf + 2; if (ibuf >= 3) ibuf -= 3;
            gemm_issue(sbase, ibuf, tid, A, B, rowBase, colBase, ch + 2);
        }

        const uint32_t aB = sbase + buf * G_STAGE_B;
        const uint32_t bB = aB + TILE_B;

#pragma unroll
        for (int ks = 0; ks < 4; ks++) {
            const int k0 = ks * 16;
            uint32_t af[2][4];
#pragma unroll
            for (int mt = 0; mt < 2; mt++) {
                uint32_t off = (m0 + mt * 16 + lr) * GROWB + (k0 + lk) * 2;
                LDSM_X4(af[mt][0], af[mt][1], af[mt][2], af[mt][3], aB + off);
            }
            uint32_t bf[8][2];
#pragma unroll
            for (int jp = 0; jp < 4; jp++) {
                uint32_t off = (n0 + jp * 16 + lr) * GROWB + (k0 + lk) * 2;
                uint32_t r0, r1, r2, r3;
                LDSM_X4(r0, r1, r2, r3, bB + off);
                bf[2 * jp][0] = r0; bf[2 * jp][1] = r2;
                bf[2 * jp + 1][0] = r1; bf[2 * jp + 1][1] = r3;
            }
#pragma unroll
            for (int mt = 0; mt < 2; mt++)
#pragma unroll
                for (int nt = 0; nt < 8; nt++) MMA_F16(acc[mt][nt], af[mt], bf[nt]);
        }
        buf = (buf == 2) ? 0 : buf + 1;
    }

    const int cr = lane >> 2;
    const int cc = (lane & 3) * 2;
#pragma unroll
    for (int mt = 0; mt < 2; mt++) {
#pragma unroll
        for (int nt = 0; nt < 8; nt++) {
            const int row = rowBase + m0 + mt * 16 + cr;
            const int col = colBase + n0 + nt * 8 + cc;
            if (OUT_MODE == 2) {
                *(uint32_t*)(Cf + (size_t)row * Dmodel + col) =
                    pack_f16(acc[mt][nt][0] * oscale, acc[mt][nt][1] * oscale);
                *(uint32_t*)(Cf + (size_t)(row + 8) * Dmodel + col) =
                    pack_f16(acc[mt][nt][2] * oscale, acc[mt][nt][3] * oscale);
            } else {
                *(float2*)&C[(size_t)row * Dmodel + col] = make_float2(acc[mt][nt][0], acc[mt][nt][1]);
                *(float2*)&C[(size_t)(row + 8) * Dmodel + col] = make_float2(acc[mt][nt][2], acc[mt][nt][3]);
            }
        }
    }
}

__global__ __launch_bounds__(256, 2) void gemm_qkv() {
    const int z = blockIdx.z;
    const unsigned short* B = (z == 0) ? g_wq : (z == 1) ? g_wk : g_wv;
    unsigned short* cf = (z == 0) ? g_qhi : (z == 1) ? g_khi : g_vhi;
    const float osc = (z == 0) ? (1.4426950408889634f * 0.08838834764831845f) : 1.0f;
    gemm_core<2>(g_xhi, B, nullptr, cf, osc);
}

__global__ __launch_bounds__(256, 2) void gemm_wo(float* __restrict__ out) {
    gemm_core<0>(g_yhi, g_wo, out, nullptr, 1.0f);
}

// ---------------------------------------------------------------------------
// Flash attention: unchanged from round 16.
// ---------------------------------------------------------------------------
#define ASTRIDE 272
#define ATILE_B (64 * ASTRIDE)         // 17408
#define ASTAGE_B (2 * ATILE_B)         // 34816: K, V
#define ATTN_SMEM (2 * ASTAGE_B)       // 69632 -> 3 CTAs/SM

__device__ __forceinline__ void attn_issue_kv(uint32_t sbase, int buf, int tid,
                                              size_t hbase, int kt)
{
    const unsigned short* srcs[2] = {g_khi, g_vhi};
    const uint32_t stage = sbase + buf * ASTAGE_B;
#pragma unroll
    for (int t = 0; t < 2; t++) {
        const unsigned short* src = srcs[t] + hbase + (size_t)(kt * 64) * Dmodel;
        const uint32_t dstT = stage + t * ATILE_B;
#pragma unroll
        for (int it = 0; it < 8; it++) {
            int idx = it * 128 + tid;
            int r = idx >> 4;
            int j = idx & 15;
            CP_ASYNC16(dstT + r * ASTRIDE + j * 16, src + (size_t)r * Dmodel + j * 8);
        }
    }
    CP_COMMIT();
}

__global__ __launch_bounds__(128, 3) void attn_mma()
{
    extern __shared__ char smem[];
    const uint32_t sbase = smem_to_u32(smem);
    const int tid = threadIdx.x;
    const int wid = tid >> 5;
    const int lane = tid & 31;

    const int qt = (gridDim.x - 1) - blockIdx.x;   // heavy tiles first
    const int h = blockIdx.y;
    const int b = blockIdx.z;
    const size_t hbase = ((size_t)b * Sseq) * Dmodel + (size_t)h * HDdim;

    const int lr = (lane & 7) + (lane & 8);
    const int lk = (lane >> 4) << 3;

    // stage Q (64 x 128 fp16, pre-scaled) through stage0 smem into frags
    {
#pragma unroll
        for (int it = 0; it < 8; it++) {
            int idx = it * 128 + tid;
            int r = idx >> 4;
            int j = idx & 15;
            const size_t goff = hbase + (size_t)(qt * 64 + r) * Dmodel + j * 8;
            CP_ASYNC16(sbase + r * ASTRIDE + j * 16, g_qhi + goff);
        }
        CP_COMMIT(); CP_WAIT0();
        __syncthreads();
    }
    uint32_t qf[8][4];
#pragma unroll
    for (int ks = 0; ks < 8; ks++) {
        uint32_t off = (wid * 16 + lr) * ASTRIDE + (ks * 16 + lk) * 2;
        LDSM_X4(qf[ks][0], qf[ks][1], qf[ks][2], qf[ks][3], sbase + off);
    }
    __syncthreads();

    float oacc[16][4];
#pragma unroll
    for (int nt = 0; nt < 16; nt++)
#pragma unroll
        for (int q = 0; q < 4; q++) oacc[nt][q] = 0.f;
    float lacc[4] = {0.f, 0.f, 0.f, 0.f};
    float m0 = -1e30f, m1 = -1e30f;

    const uint32_t onesf[2] = {0x3C003C00u, 0x3C003C00u};  // all-ones fp16 B-frag

    const int nkt = qt + 1;
    attn_issue_kv(sbase, 0, tid, hbase, 0);
    if (nkt > 1) attn_issue_kv(sbase, 1, tid, hbase, 1);

    const int row0 = qt * 64 + wid * 16 + (lane >> 2);

    for (int kt = 0; kt < nkt; kt++) {
        if (kt + 1 < nkt) { CP_WAIT1(); } else { CP_WAIT0(); }
        __syncthreads();

        const uint32_t stage = sbase + (kt & 1) * ASTAGE_B;
        const uint32_t kB = stage;
        const uint32_t vB = stage + ATILE_B;

        // S = Q K^T in fp16-acc (reg0 = row r cols c,c+1; reg1 = row r+8)
        uint32_t sacc[8][2];
#pragma unroll
        for (int nt = 0; nt < 8; nt++) { sacc[nt][0] = 0u; sacc[nt][1] = 0u; }
#pragma unroll
        for (int ks = 0; ks < 8; ks++) {
            uint32_t bh[8][2];
#pragma unroll
            for (int jp = 0; jp < 4; jp++) {
                uint32_t off = (jp * 16 + lr) * ASTRIDE + (ks * 16 + lk) * 2;
                uint32_t r0, r1, r2, r3;
                LDSM_X4(r0, r1, r2, r3, kB + off);
                bh[2 * jp][0] = r0; bh[2 * jp][1] = r2;
                bh[2 * jp + 1][0] = r1; bh[2 * jp + 1][1] = r3;
            }
#pragma unroll
            for (int nt = 0; nt < 8; nt++) MMA_F16_H(sacc[nt], qf[ks], bh[nt]);
        }

        // causal mask on the diagonal k-tile (fp16 -inf = 0xFC00)
        if (kt == qt) {
            const int colA = kt * 64 + 2 * (lane & 3);
#pragma unroll
            for (int nt = 0; nt < 8; nt++) {
                const int c = colA + nt * 8;
                uint32_t w0 = sacc[nt][0], w1 = sacc[nt][1];
                if (c > row0)     w0 = (w0 & 0xFFFF0000u) | 0x0000FC00u;
                if (c + 1 > row0) w0 = (w0 & 0x0000FFFFu) | 0xFC000000u;
                if (c > row0 + 8)     w1 = (w1 & 0xFFFF0000u) | 0x0000FC00u;
                if (c + 1 > row0 + 8) w1 = (w1 & 0x0000FFFFu) | 0xFC000000u;
                sacc[nt][0] = w0; sacc[nt][1] = w1;
            }
        }

        // row max in f16x2
        uint32_t ux0 = 0xFC00FC00u, ux1 = 0xFC00FC00u;
#pragma unroll
        for (int nt = 0; nt < 8; nt++) {
            ux0 = hmax2u(ux0, sacc[nt][0]);
            ux1 = hmax2u(ux1, sacc[nt][1]);
        }
        {
            __half2 t0 = *reinterpret_cast<__half2*>(&ux0);
            t0 = __hmax2(t0, __lowhigh2highlow(t0));
            ux0 = *reinterpret_cast<uint32_t*>(&t0);
            __half2 t1 = *reinterpret_cast<__half2*>(&ux1);
            t1 = __hmax2(t1, __lowhigh2highlow(t1));
            ux1 = *reinterpret_cast<uint32_t*>(&t1);
        }
        ux0 = hmax2u(ux0, __shfl_xor_sync(0xffffffffu, ux0, 1));
        ux0 = hmax2u(ux0, __shfl_xor_sync(0xffffffffu, ux0, 2));
        ux1 = hmax2u(ux1, __shfl_xor_sync(0xffffffffu, ux1, 1));
        ux1 = hmax2u(ux1, __shfl_xor_sync(0xffffffffu, ux1, 2));
        float mx0 = __half2float(__low2half(*reinterpret_cast<__half2*>(&ux0)));
        float mx1 = __half2float(__low2half(*reinterpret_cast<__half2*>(&ux1)));

        float mn0 = fmaxf(m0, mx0), mn1 = fmaxf(m1, mx1);
        float a0 = fast_ex2(m0 - mn0), a1 = fast_ex2(m1 - mn1);
#pragma unroll
        for (int nt = 0; nt < 16; nt++) {
            oacc[nt][0] *= a0; oacc[nt][1] *= a0;
            oacc[nt][2] *= a1; oacc[nt][3] *= a1;
        }
        lacc[0] *= a0; lacc[1] *= a0; lacc[2] *= a1; lacc[3] *= a1;
        m0 = mn0; m1 = mn1;

        __half2 mh0 = __float2half2_rn(mn0);
        __half2 mh1 = __float2half2_rn(mn1);
        const uint32_t mu0 = *reinterpret_cast<uint32_t*>(&mh0);
        const uint32_t mu1 = *reinterpret_cast<uint32_t*>(&mh1);

        // O += P V; l += P * ones. p = 2^(s-m) directly in f16x2.
#pragma unroll
        for (int kstep = 0; kstep < 4; kstep++) {
            uint32_t ph[4];
            ph[0] = h2exp2_sub(sacc[2 * kstep][0], mu0);
            ph[1] = h2exp2_sub(sacc[2 * kstep][1], mu1);
            ph[2] = h2exp2_sub(sacc[2 * kstep + 1][0], mu0);
            ph[3] = h2exp2_sub(sacc[2 * kstep + 1][1], mu1);
            MMA_F16(lacc, ph, onesf);
#pragma unroll
            for (int db = 0; db < 2; db++) {
                uint32_t bv[8][2];
#pragma unroll
                for (int dpi = 0; dpi < 4; dpi++) {
                    const int dp = db * 4 + dpi;
                    uint32_t off = (kstep * 16 + lr) * ASTRIDE + (dp * 16 + lk) * 2;
                    uint32_t v0, v1, v2, v3;
                    LDSM_X4_T(v0, v1, v2, v3, vB + off);
                    bv[2 * dpi][0] = v0; bv[2 * dpi][1] = v1;
                    bv[2 * dpi + 1][0] = v2; bv[2 * dpi + 1][1] = v3;
                }
#pragma unroll
                for (int dpi = 0; dpi < 4; dpi++) {
                    MMA_F16(oacc[2 * (db * 4 + dpi)], ph, bv[2 * dpi]);
                    MMA_F16(oacc[2 * (db * 4 + dpi) + 1], ph, bv[2 * dpi + 1]);
                }
            }
        }

        __syncthreads();
        if (kt + 2 < nkt)
            attn_issue_kv(sbase, kt & 1, tid, hbase, kt + 2);
    }

    const float inv0 = 1.f / lacc[0];
    const float inv1 = 1.f / lacc[2];
#pragma unroll
    for (int nt = 0; nt < 16; nt++) {
        const int col = nt * 8 + 2 * (lane & 3);
        const size_t i0 = ((size_t)b * Sseq + row0) * Dmodel + h * HDdim + col;
        const size_t i1 = ((size_t)b * Sseq + row0 + 8) * Dmodel + h * HDdim + col;
        *(uint32_t*)(g_yhi + i0) = pack_f16(oacc[nt][0] * inv0, oacc[nt][1] * inv0);
        *(uint32_t*)(g_yhi + i1) = pack_f16(oacc[nt][2] * inv1, oacc[nt][3] * inv1);
    }
}

// ---------------------------------------------------------------------------
// launch
// ---------------------------------------------------------------------------
extern "C" void kernel_launch(void* const* d_in, const int* in_sizes, int n_in,
                              void* d_out, int out_size)
{
    (void)in_sizes; (void)n_in; (void)out_size;
    const float* x  = (const float*)d_in[0];
    const float* Wq = (const float*)d_in[2];
    const float* Wk = (const float*)d_in[3];
    const float* Wv = (const float*)d_in[4];
    const float* Wo = (const float*)d_in[5];
    float* out = (float*)d_out;

    cudaFuncSetAttribute(gemm_qkv, cudaFuncAttributeMaxDynamicSharedMemorySize, G_SMEM);
    cudaFuncSetAttribute(gemm_wo, cudaFuncAttributeMaxDynamicSharedMemorySize, G_SMEM);
    cudaFuncSetAttribute(attn_mma, cudaFuncAttributeMaxDynamicSharedMemorySize, ATTN_SMEM);

    // fused converts: z=0 -> x (1M uint4 outs), z=1..4 -> weights (512K each)
    conv_all<<<dim3(CONV_OUT4_X / 1024, 1, 5), 256>>>(x, Wq, Wk, Wv, Wo);

    gemm_qkv<<<dim3(Dmodel / 128, Mrows / 128, 3), 256, G_SMEM>>>();
    attn_mma<<<dim3(Sseq / 64, Hheads, Bsz), 128, ATTN_SMEM>>>();
    gemm_wo<<<dim3(Dmodel / 128, Mrows / 128, 1), 256, G_SMEM>>>(out);
}